// round 2
// baseline (speedup 1.0000x reference)
#include <cuda_runtime.h>
#include <math.h>

#define B_  4
#define N_  4096
#define C_  1024
#define H_  16
#define D_  64
#define KL_ 256
#define C3_ 3072

// Scratch (allocation-free rule: __device__ globals)
__device__ float g_qkv[B_ * N_ * C3_];        // 192 MB: [b, n, {q|k|v} h d]
__device__ float g_klm[B_ * H_ * KL_ * D_];   // 4 MB
__device__ float g_vlm[B_ * H_ * KL_ * D_];   // 4 MB
__device__ float g_ao [B_ * H_ * N_ * D_];    // 64 MB: attention out, (B,H,N,d) flat

// ---------------------------------------------------------------------------
// GEMM NT: C[M,Nc] = A[M,K] @ Bm[Nc,K]^T (+bias).  M,Nc % 128 == 0, K % 16 == 0
// 128x128 block tile, 8x8 per thread, 256 threads, register prefetch.
// ---------------------------------------------------------------------------
__global__ __launch_bounds__(256)
void gemm_nt_kernel(const float* __restrict__ A, const float* __restrict__ Bm,
                    float* __restrict__ Cm, int M, int Nc, int K,
                    const float* __restrict__ bias)
{
    __shared__ float AsT[16][132];
    __shared__ float BsT[16][132];

    const int tid = threadIdx.x;
    const int m0 = blockIdx.y * 128;
    const int n0 = blockIdx.x * 128;

    const int lrow = tid >> 2;          // 0..63
    const int lkg  = (tid & 3) << 2;    // 0,4,8,12

    const float* Ap = A  + (m0 + lrow) * K + lkg;
    const float* Bp = Bm + (n0 + lrow) * K + lkg;

    float4 ra0 = *(const float4*)(Ap);
    float4 ra1 = *(const float4*)(Ap + 64 * K);
    float4 rb0 = *(const float4*)(Bp);
    float4 rb1 = *(const float4*)(Bp + 64 * K);

    const int ar = (tid >> 4) << 3;     // 0..120
    const int bc = (tid & 15) << 3;     // 0..120

    float acc[8][8];
#pragma unroll
    for (int i = 0; i < 8; i++)
#pragma unroll
        for (int j = 0; j < 8; j++) acc[i][j] = 0.f;

    for (int k0 = 0; k0 < K; k0 += 16) {
        __syncthreads();
        AsT[lkg + 0][lrow]      = ra0.x;  AsT[lkg + 1][lrow]      = ra0.y;
        AsT[lkg + 2][lrow]      = ra0.z;  AsT[lkg + 3][lrow]      = ra0.w;
        AsT[lkg + 0][lrow + 64] = ra1.x;  AsT[lkg + 1][lrow + 64] = ra1.y;
        AsT[lkg + 2][lrow + 64] = ra1.z;  AsT[lkg + 3][lrow + 64] = ra1.w;
        BsT[lkg + 0][lrow]      = rb0.x;  BsT[lkg + 1][lrow]      = rb0.y;
        BsT[lkg + 2][lrow]      = rb0.z;  BsT[lkg + 3][lrow]      = rb0.w;
        BsT[lkg + 0][lrow + 64] = rb1.x;  BsT[lkg + 1][lrow + 64] = rb1.y;
        BsT[lkg + 2][lrow + 64] = rb1.z;  BsT[lkg + 3][lrow + 64] = rb1.w;
        __syncthreads();

        if (k0 + 16 < K) {
            ra0 = *(const float4*)(Ap + k0 + 16);
            ra1 = *(const float4*)(Ap + k0 + 16 + 64 * K);
            rb0 = *(const float4*)(Bp + k0 + 16);
            rb1 = *(const float4*)(Bp + k0 + 16 + 64 * K);
        }

#pragma unroll
        for (int kk = 0; kk < 16; kk++) {
            float4 a0 = *(const float4*)&AsT[kk][ar];
            float4 a1 = *(const float4*)&AsT[kk][ar + 4];
            float4 b0 = *(const float4*)&BsT[kk][bc];
            float4 b1 = *(const float4*)&BsT[kk][bc + 4];
            float av[8] = {a0.x, a0.y, a0.z, a0.w, a1.x, a1.y, a1.z, a1.w};
            float bv[8] = {b0.x, b0.y, b0.z, b0.w, b1.x, b1.y, b1.z, b1.w};
#pragma unroll
            for (int i = 0; i < 8; i++)
#pragma unroll
                for (int j = 0; j < 8; j++)
                    acc[i][j] += av[i] * bv[j];
        }
    }

    float bb[8];
#pragma unroll
    for (int j = 0; j < 8; j++) bb[j] = bias ? bias[n0 + bc + j] : 0.f;

#pragma unroll
    for (int i = 0; i < 8; i++) {
        float* crow = Cm + (m0 + ar + i) * Nc + n0 + bc;
        float4 s0 = make_float4(acc[i][0] + bb[0], acc[i][1] + bb[1],
                                acc[i][2] + bb[2], acc[i][3] + bb[3]);
        float4 s1 = make_float4(acc[i][4] + bb[4], acc[i][5] + bb[5],
                                acc[i][6] + bb[6], acc[i][7] + bb[7]);
        *(float4*)(crow)     = s0;
        *(float4*)(crow + 4) = s1;
    }
}

// ---------------------------------------------------------------------------
// Landmark projection: k_lm[bh,k,d] = sum_n E[h,k,n] * K[b,n,h,d]  (same for V)
// Block = one 64x64 output tile of one (bh, which) pair; contraction K = 4096.
// grid.x = 64(bh) * 4(k-tile) * 2(which) = 512 blocks, 256 threads, 4x4 micro.
// ---------------------------------------------------------------------------
__global__ __launch_bounds__(256)
void landmark_kernel(const float* __restrict__ E, const float* __restrict__ qkv,
                     float* __restrict__ klm, float* __restrict__ vlm)
{
    const int bid   = blockIdx.x;
    const int which = bid & 1;          // 0 = K, 1 = V
    const int kb    = (bid >> 1) & 3;   // k-tile (64 rows of 256)
    const int bh    = bid >> 3;         // 0..63
    const int b = bh >> 4, h = bh & 15;

    const float* Ea   = E + (h * KL_ + kb * 64) * N_;
    const float* Bsrc = qkv + (b * N_) * C3_ + (1 + which) * C_ + h * D_;
    float* outp = (which ? vlm : klm) + (bh * KL_ + kb * 64) * D_;

    __shared__ float AsT[16][68];   // [n][krow]  (pitch 68: 16B aligned, low conflict)
    __shared__ float Bs[16][64];    // [n][d]

    const int tid = threadIdx.x;
    const int arow = tid >> 2;            // 0..63 (E row in tile)
    const int ag   = (tid & 3) << 2;      // n group
    const int nr   = tid >> 4;            // 0..15 (qkv row in chunk)
    const int dg   = (tid & 15) << 2;     // d group

    const int kr = (tid >> 4) << 2;       // out row group (0..60)
    const int dc = (tid & 15) << 2;       // out col group (0..60)

    float4 ra = *(const float4*)(Ea + arow * N_ + ag);
    float4 rb = *(const float4*)(Bsrc + nr * C3_ + dg);

    float acc[4][4];
#pragma unroll
    for (int i = 0; i < 4; i++)
#pragma unroll
        for (int j = 0; j < 4; j++) acc[i][j] = 0.f;

    for (int n0 = 0; n0 < N_; n0 += 16) {
        __syncthreads();
        AsT[ag + 0][arow] = ra.x;  AsT[ag + 1][arow] = ra.y;
        AsT[ag + 2][arow] = ra.z;  AsT[ag + 3][arow] = ra.w;
        *(float4*)&Bs[nr][dg] = rb;
        __syncthreads();

        if (n0 + 16 < N_) {
            ra = *(const float4*)(Ea + arow * N_ + n0 + 16 + ag);
            rb = *(const float4*)(Bsrc + (n0 + 16 + nr) * C3_ + dg);
        }

#pragma unroll
        for (int nn = 0; nn < 16; nn++) {
            float4 a = *(const float4*)&AsT[nn][kr];
            float4 v = *(const float4*)&Bs[nn][dc];
            float avv[4] = {a.x, a.y, a.z, a.w};
            float bvv[4] = {v.x, v.y, v.z, v.w};
#pragma unroll
            for (int i = 0; i < 4; i++)
#pragma unroll
                for (int j = 0; j < 4; j++)
                    acc[i][j] += avv[i] * bvv[j];
        }
    }

#pragma unroll
    for (int i = 0; i < 4; i++) {
        float4 s = make_float4(acc[i][0], acc[i][1], acc[i][2], acc[i][3]);
        *(float4*)&outp[(kr + i) * D_ + dc] = s;
    }
}

// ---------------------------------------------------------------------------
// Fused attention: per (bh) block keeps k_lm^T and v_lm in smem, loops over
// 32-row q tiles: S = (q*0.125) @ klm^T -> softmax(rows) -> O = P @ vlm / sum
// smem: klmT[64][256] | vlm[256][64] | qT[64][32] | S[32][264] | recip[32]
// ---------------------------------------------------------------------------
#define SP_ 264                                  // S row pitch (floats)
#define ATTN_SMEM_FLOATS (16384 + 16384 + 2048 + 32 * SP_ + 32)
#define ATTN_SMEM_BYTES  (ATTN_SMEM_FLOATS * 4)  // 173,184 B

__global__ __launch_bounds__(256)
void attn_kernel(const float* __restrict__ qkv, const float* __restrict__ klm,
                 const float* __restrict__ vlm_g, float* __restrict__ ao)
{
    extern __shared__ float sm[];
    float* klmT = sm;                 // [d][k]   d-major
    float* vlm  = sm + 16384;         // [k][d]
    float* qT   = sm + 32768;         // [d][r]
    float* sS   = sm + 34816;         // [r][k]   pitch SP_
    float* rec  = sm + 34816 + 32 * SP_;

    const int bh = blockIdx.x;
    const int b = bh >> 4, h = bh & 15;
    const int tid = threadIdx.x;

    // Load k_lm transposed (thread tid owns landmark row k=tid) and v_lm direct.
    {
        const float* src = klm + (bh * KL_ + tid) * D_;
#pragma unroll
        for (int j = 0; j < 16; j++) {
            float4 v = *(const float4*)(src + j * 4);
            klmT[(j * 4 + 0) * KL_ + tid] = v.x;
            klmT[(j * 4 + 1) * KL_ + tid] = v.y;
            klmT[(j * 4 + 2) * KL_ + tid] = v.z;
            klmT[(j * 4 + 3) * KL_ + tid] = v.w;
        }
        const float4* vsrc = (const float4*)(vlm_g + bh * KL_ * D_);
        float4* vdst = (float4*)vlm;
#pragma unroll
        for (int j = 0; j < 16; j++) vdst[j * 256 + tid] = vsrc[j * 256 + tid];
    }

    const int rg  = (tid >> 5) << 2;   // 4 rows per warp
    const int cg  = (tid & 31) << 3;   // 8 landmarks per lane (phase 1)
    const int cg2 = (tid & 31) << 1;   // 2 d-cols per lane (phase 2)
    const int w = tid >> 5, lane = tid & 31;

    const int nb = blockIdx.y * 128;   // 128 rows per block (gridDim.y = 32)

    for (int t0 = nb; t0 < nb + 128; t0 += 32) {
        // load qT (scaled by 1/sqrt(d)); thread: row = tid&31, d-seg = tid>>5
        {
            const int r = tid & 31, seg = (tid >> 5) << 3;
            const float* qsrc = qkv + (b * N_ + t0 + r) * C3_ + h * D_ + seg;
            float4 v0 = *(const float4*)(qsrc);
            float4 v1 = *(const float4*)(qsrc + 4);
            qT[(seg + 0) * 32 + r] = v0.x * 0.125f;
            qT[(seg + 1) * 32 + r] = v0.y * 0.125f;
            qT[(seg + 2) * 32 + r] = v0.z * 0.125f;
            qT[(seg + 3) * 32 + r] = v0.w * 0.125f;
            qT[(seg + 4) * 32 + r] = v1.x * 0.125f;
            qT[(seg + 5) * 32 + r] = v1.y * 0.125f;
            qT[(seg + 6) * 32 + r] = v1.z * 0.125f;
            qT[(seg + 7) * 32 + r] = v1.w * 0.125f;
        }
        __syncthreads();

        // ---- Phase 1: S[32][256] = qT^T @ klmT ----
        float a1[4][8];
#pragma unroll
        for (int i = 0; i < 4; i++)
#pragma unroll
            for (int j = 0; j < 8; j++) a1[i][j] = 0.f;

#pragma unroll 4
        for (int d = 0; d < 64; d++) {
            float4 qv = *(const float4*)&qT[d * 32 + rg];
            float4 k0 = *(const float4*)&klmT[d * KL_ + cg];
            float4 k1 = *(const float4*)&klmT[d * KL_ + cg + 4];
            float qa[4] = {qv.x, qv.y, qv.z, qv.w};
            float kb[8] = {k0.x, k0.y, k0.z, k0.w, k1.x, k1.y, k1.z, k1.w};
#pragma unroll
            for (int i = 0; i < 4; i++)
#pragma unroll
                for (int j = 0; j < 8; j++)
                    a1[i][j] += qa[i] * kb[j];
        }
#pragma unroll
        for (int i = 0; i < 4; i++) {
            *(float4*)&sS[(rg + i) * SP_ + cg] =
                make_float4(a1[i][0], a1[i][1], a1[i][2], a1[i][3]);
            *(float4*)&sS[(rg + i) * SP_ + cg + 4] =
                make_float4(a1[i][4], a1[i][5], a1[i][6], a1[i][7]);
        }
        __syncthreads();

        // ---- Softmax per row (warp w handles rows 4w..4w+3) ----
#pragma unroll
        for (int i = 0; i < 4; i++) {
            const int r = w * 4 + i;
            float* row = &sS[r * SP_];
            float v[8];
#pragma unroll
            for (int j = 0; j < 8; j++) v[j] = row[lane + 32 * j];
            float m = v[0];
#pragma unroll
            for (int j = 1; j < 8; j++) m = fmaxf(m, v[j]);
#pragma unroll
            for (int off = 16; off > 0; off >>= 1)
                m = fmaxf(m, __shfl_xor_sync(0xffffffffu, m, off));
            float s = 0.f;
#pragma unroll
            for (int j = 0; j < 8; j++) { v[j] = __expf(v[j] - m); s += v[j]; }
#pragma unroll
            for (int off = 16; off > 0; off >>= 1)
                s += __shfl_xor_sync(0xffffffffu, s, off);
#pragma unroll
            for (int j = 0; j < 8; j++) row[lane + 32 * j] = v[j];
            if (lane == 0) rec[r] = 1.f / s;
        }
        __syncthreads();

        // ---- Phase 2: O[32][64] = P @ vlm, scaled by rec[row] ----
        float a2[4][2];
#pragma unroll
        for (int i = 0; i < 4; i++) { a2[i][0] = 0.f; a2[i][1] = 0.f; }

#pragma unroll 2
        for (int k = 0; k < KL_; k += 4) {
            float4 av0 = *(const float4*)&sS[(rg + 0) * SP_ + k];
            float4 av1 = *(const float4*)&sS[(rg + 1) * SP_ + k];
            float4 av2 = *(const float4*)&sS[(rg + 2) * SP_ + k];
            float4 av3 = *(const float4*)&sS[(rg + 3) * SP_ + k];
            float am[4][4] = {{av0.x, av0.y, av0.z, av0.w},
                              {av1.x, av1.y, av1.z, av1.w},
                              {av2.x, av2.y, av2.z, av2.w},
                              {av3.x, av3.y, av3.z, av3.w}};
#pragma unroll
            for (int kk = 0; kk < 4; kk++) {
                float2 vv = *(const float2*)&vlm[(k + kk) * D_ + cg2];
#pragma unroll
                for (int i = 0; i < 4; i++) {
                    a2[i][0] += am[i][kk] * vv.x;
                    a2[i][1] += am[i][kk] * vv.y;
                }
            }
        }

        float* outp = ao + (bh * N_ + t0 + rg) * D_ + cg2;
#pragma unroll
        for (int i = 0; i < 4; i++) {
            float rc = rec[rg + i];
            float2 st = make_float2(a2[i][0] * rc, a2[i][1] * rc);
            *(float2*)(outp + i * D_) = st;
        }
        __syncthreads();
    }
}

// ---------------------------------------------------------------------------
extern "C" void kernel_launch(void* const* d_in, const int* in_sizes, int n_in,
                              void* d_out, int out_size)
{
    (void)in_sizes; (void)n_in; (void)out_size;
    const float* x     = (const float*)d_in[0];
    const float* Wqkv  = (const float*)d_in[1];
    const float* E     = (const float*)d_in[2];
    const float* Wproj = (const float*)d_in[3];
    const float* bproj = (const float*)d_in[4];
    float* out = (float*)d_out;

    void *p_qkv, *p_klm, *p_vlm, *p_ao;
    cudaGetSymbolAddress(&p_qkv, g_qkv);
    cudaGetSymbolAddress(&p_klm, g_klm);
    cudaGetSymbolAddress(&p_vlm, g_vlm);
    cudaGetSymbolAddress(&p_ao,  g_ao);
    float* qkv = (float*)p_qkv;
    float* klm = (float*)p_klm;
    float* vlm = (float*)p_vlm;
    float* ao  = (float*)p_ao;

    cudaFuncSetAttribute(attn_kernel,
                         cudaFuncAttributeMaxDynamicSharedMemorySize,
                         ATTN_SMEM_BYTES);

    const int M = B_ * N_;  // 16384

    // 1) qkv = x @ Wqkv^T
    gemm_nt_kernel<<<dim3(C3_ / 128, M / 128), 256>>>(x, Wqkv, qkv, M, C3_, C_, nullptr);

    // 2) k_lm / v_lm landmark projections
    landmark_kernel<<<512, 256>>>(E, qkv, klm, vlm);

    // 3) fused Linformer attention -> ao in (B,H,N,d) flat order
    attn_kernel<<<dim3(B_ * H_, 32), 256, ATTN_SMEM_BYTES>>>(qkv, klm, vlm, ao);

    // 4) out = ao @ Wproj^T + bproj  (ao flat == (B,N,C) per reference reshape)
    gemm_nt_kernel<<<dim3(C_ / 128, M / 128), 256>>>(ao, Wproj, out, M, C_, C_, bproj);
}

// round 4
// speedup vs baseline: 1.6188x; 1.6188x over previous
#include <cuda_runtime.h>
#include <cuda_bf16.h>
#include <cstdint>
#include <math.h>

#define B_  4
#define N_  4096
#define C_  1024
#define H_  16
#define D_  64
#define KL_ 256
#define C3_ 3072

// fp32 scratch
__device__ float g_qkv[B_ * N_ * C3_];        // [b, n, {q|k|v} h d]
__device__ float g_klm[B_ * H_ * KL_ * D_];
__device__ float g_vlm[B_ * H_ * KL_ * D_];
__device__ float g_ao [B_ * H_ * N_ * D_];    // (B,H,N,d) flat

// split-precision bf16 scratch (hi/lo)
__device__ __nv_bfloat16 g_xh [B_ * N_ * C_];
__device__ __nv_bfloat16 g_xl [B_ * N_ * C_];
__device__ __nv_bfloat16 g_w3h[C3_ * C_];
__device__ __nv_bfloat16 g_w3l[C3_ * C_];
__device__ __nv_bfloat16 g_aoh[B_ * N_ * C_];
__device__ __nv_bfloat16 g_aol[B_ * N_ * C_];
__device__ __nv_bfloat16 g_wph[C_ * C_];
__device__ __nv_bfloat16 g_wpl[C_ * C_];

// ---------------------------------------------------------------------------
// helpers
// ---------------------------------------------------------------------------
__device__ __forceinline__ uint32_t smem_u32(const void* p) {
    uint32_t a;
    asm("{ .reg .u64 t; cvta.to.shared.u64 t, %1; cvt.u32.u64 %0, t; }"
        : "=r"(a) : "l"(p));
    return a;
}
__device__ __forceinline__ void cp16(uint32_t dst, const void* src) {
    asm volatile("cp.async.cg.shared.global [%0], [%1], 16;"
                 :: "r"(dst), "l"(src) : "memory");
}
__device__ __forceinline__ void cp_commit() {
    asm volatile("cp.async.commit_group;" ::: "memory");
}
#define CP_WAIT(n) asm volatile("cp.async.wait_group %0;" :: "n"(n) : "memory")

// mma.sync m16n8k16 bf16 (baseline PTX ISA — works on sm_103 non-'a' target)
#define MMA16816(d, a, b) \
    asm volatile( \
        "mma.sync.aligned.m16n8k16.row.col.f32.bf16.bf16.f32 " \
        "{%0,%1,%2,%3}, {%4,%5,%6,%7}, {%8,%9}, {%0,%1,%2,%3};" \
        : "+f"((d)[0]), "+f"((d)[1]), "+f"((d)[2]), "+f"((d)[3]) \
        : "r"((a)[0]), "r"((a)[1]), "r"((a)[2]), "r"((a)[3]), \
          "r"((b)[0]), "r"((b)[1]))

// ---------------------------------------------------------------------------
// split fp32 -> (hi, lo) bf16
// ---------------------------------------------------------------------------
__global__ __launch_bounds__(256)
void split_kernel(const float* __restrict__ in, __nv_bfloat16* __restrict__ hi,
                  __nv_bfloat16* __restrict__ lo, int n4)
{
    int i = blockIdx.x * blockDim.x + threadIdx.x;
    if (i >= n4) return;
    float4 v = ((const float4*)in)[i];
    __nv_bfloat16 h0 = __float2bfloat16(v.x);
    __nv_bfloat16 h1 = __float2bfloat16(v.y);
    __nv_bfloat16 h2 = __float2bfloat16(v.z);
    __nv_bfloat16 h3 = __float2bfloat16(v.w);
    __nv_bfloat16 l0 = __float2bfloat16(v.x - __bfloat162float(h0));
    __nv_bfloat16 l1 = __float2bfloat16(v.y - __bfloat162float(h1));
    __nv_bfloat16 l2 = __float2bfloat16(v.z - __bfloat162float(h2));
    __nv_bfloat16 l3 = __float2bfloat16(v.w - __bfloat162float(h3));
    __nv_bfloat162* hp = (__nv_bfloat162*)hi;
    __nv_bfloat162* lp = (__nv_bfloat162*)lo;
    hp[2 * i]     = __halves2bfloat162(h0, h1);
    hp[2 * i + 1] = __halves2bfloat162(h2, h3);
    lp[2 * i]     = __halves2bfloat162(l0, l1);
    lp[2 * i + 1] = __halves2bfloat162(l2, l3);
}

// ---------------------------------------------------------------------------
// mma.sync split-bf16 GEMM: C[M,Nc] = A[M,1024] @ B[Nc,1024]^T (+bias)
// CTA tile 128x128, BK=32, 8 warps (4m x 2n), warp tile 32x64.
// cp.async double-buffered. Fragments via plain LDS (documented mapping).
// ---------------------------------------------------------------------------
#define GK_    1024
#define BKC_   32
#define NCH_   (GK_ / BKC_)       // 32 chunks
#define PADK_  40                 // smem row pitch in elems (80B, conflict-free)
#define TILEB_ (128 * PADK_ * 2)  // 10240 B per tile
#define STGB_  (4 * TILEB_)       // Ah|Al|Bh|Bl = 40960 B
#define GSMEM  (2 * STGB_)        // 81920 B

__device__ __forceinline__ void load_stage(
    uint32_t sb, const __nv_bfloat16* __restrict__ Ah, const __nv_bfloat16* __restrict__ Al,
    const __nv_bfloat16* __restrict__ Bh, const __nv_bfloat16* __restrict__ Bl,
    int m0, int n0, int kof, int tid)
{
    const int r  = tid >> 1;          // 0..127
    const int hf = tid & 1;           // half of 64B row
    const uint32_t so = (uint32_t)r * (PADK_ * 2) + hf * 32;
    const size_t gA = (size_t)(m0 + r) * GK_ + kof + hf * 16;
    const size_t gB = (size_t)(n0 + r) * GK_ + kof + hf * 16;
    cp16(sb + 0 * TILEB_ + so,      Ah + gA);
    cp16(sb + 0 * TILEB_ + so + 16, Ah + gA + 8);
    cp16(sb + 1 * TILEB_ + so,      Al + gA);
    cp16(sb + 1 * TILEB_ + so + 16, Al + gA + 8);
    cp16(sb + 2 * TILEB_ + so,      Bh + gB);
    cp16(sb + 2 * TILEB_ + so + 16, Bh + gB + 8);
    cp16(sb + 3 * TILEB_ + so,      Bl + gB);
    cp16(sb + 3 * TILEB_ + so + 16, Bl + gB + 8);
}

__global__ __launch_bounds__(256)
void gemm_mma_kernel(const __nv_bfloat16* __restrict__ Ah, const __nv_bfloat16* __restrict__ Al,
                     const __nv_bfloat16* __restrict__ Bh, const __nv_bfloat16* __restrict__ Bl,
                     float* __restrict__ Cm, const float* __restrict__ bias, int Nc)
{
    extern __shared__ __align__(16) char dyn[];
    const uint32_t sbase = smem_u32(dyn);

    const int tid  = threadIdx.x;
    const int warp = tid >> 5, lane = tid & 31;
    const int wm   = warp & 3;        // 0..3 -> m offset 32*wm
    const int wn   = warp >> 2;       // 0..1 -> n offset 64*wn
    const int gid  = lane >> 2;       // group (row within 8x4)
    const int tig  = lane & 3;        // thread-in-group
    const int m0 = blockIdx.y * 128;
    const int n0 = blockIdx.x * 128;

    float acc[2][8][4];
#pragma unroll
    for (int mi = 0; mi < 2; mi++)
#pragma unroll
        for (int j = 0; j < 8; j++)
#pragma unroll
            for (int q = 0; q < 4; q++) acc[mi][j][q] = 0.f;

    load_stage(sbase, Ah, Al, Bh, Bl, m0, n0, 0, tid);
    cp_commit();

    for (int c = 0; c < NCH_; c++) {
        const int st = c & 1;
        if (c + 1 < NCH_) {
            load_stage(sbase + (st ^ 1) * STGB_, Ah, Al, Bh, Bl, m0, n0,
                       (c + 1) * BKC_, tid);
            cp_commit();
            CP_WAIT(1);
        } else {
            CP_WAIT(0);
        }
        __syncthreads();

        const __nv_bfloat16* sA = (const __nv_bfloat16*)(dyn + st * STGB_);
        const __nv_bfloat16* sAl = (const __nv_bfloat16*)(dyn + st * STGB_ + TILEB_);
        const __nv_bfloat16* sB = (const __nv_bfloat16*)(dyn + st * STGB_ + 2 * TILEB_);
        const __nv_bfloat16* sBl = (const __nv_bfloat16*)(dyn + st * STGB_ + 3 * TILEB_);

#pragma unroll
        for (int kk = 0; kk < BKC_; kk += 16) {
            uint32_t rbh[8][2], rbl[8][2];
#pragma unroll
            for (int j = 0; j < 8; j++) {
                const int rb = wn * 64 + j * 8 + gid;
                rbh[j][0] = *(const uint32_t*)&sB [rb * PADK_ + kk + 2 * tig];
                rbh[j][1] = *(const uint32_t*)&sB [rb * PADK_ + kk + 2 * tig + 8];
                rbl[j][0] = *(const uint32_t*)&sBl[rb * PADK_ + kk + 2 * tig];
                rbl[j][1] = *(const uint32_t*)&sBl[rb * PADK_ + kk + 2 * tig + 8];
            }
            uint32_t ra[2][4];
#pragma unroll
            for (int mi = 0; mi < 2; mi++) {
                const int rr = wm * 32 + mi * 16 + gid;
                ra[mi][0] = *(const uint32_t*)&sA[rr * PADK_ + kk + 2 * tig];
                ra[mi][1] = *(const uint32_t*)&sA[(rr + 8) * PADK_ + kk + 2 * tig];
                ra[mi][2] = *(const uint32_t*)&sA[rr * PADK_ + kk + 2 * tig + 8];
                ra[mi][3] = *(const uint32_t*)&sA[(rr + 8) * PADK_ + kk + 2 * tig + 8];
            }
            // hi*hi and hi*lo with Ahi resident
#pragma unroll
            for (int mi = 0; mi < 2; mi++)
#pragma unroll
                for (int j = 0; j < 8; j++) {
                    MMA16816(acc[mi][j], ra[mi], rbh[j]);
                    MMA16816(acc[mi][j], ra[mi], rbl[j]);
                }
            // lo*hi: reuse ra registers for Alo
#pragma unroll
            for (int mi = 0; mi < 2; mi++) {
                const int rr = wm * 32 + mi * 16 + gid;
                ra[mi][0] = *(const uint32_t*)&sAl[rr * PADK_ + kk + 2 * tig];
                ra[mi][1] = *(const uint32_t*)&sAl[(rr + 8) * PADK_ + kk + 2 * tig];
                ra[mi][2] = *(const uint32_t*)&sAl[rr * PADK_ + kk + 2 * tig + 8];
                ra[mi][3] = *(const uint32_t*)&sAl[(rr + 8) * PADK_ + kk + 2 * tig + 8];
            }
#pragma unroll
            for (int mi = 0; mi < 2; mi++)
#pragma unroll
                for (int j = 0; j < 8; j++)
                    MMA16816(acc[mi][j], ra[mi], rbh[j]);
        }
        __syncthreads();
    }

    // epilogue
#pragma unroll
    for (int mi = 0; mi < 2; mi++) {
        const int row = m0 + wm * 32 + mi * 16 + gid;
#pragma unroll
        for (int j = 0; j < 8; j++) {
            const int col = n0 + wn * 64 + j * 8 + 2 * tig;
            float b0 = 0.f, b1 = 0.f;
            if (bias) { b0 = __ldg(bias + col); b1 = __ldg(bias + col + 1); }
            float2 s0 = make_float2(acc[mi][j][0] + b0, acc[mi][j][1] + b1);
            float2 s1 = make_float2(acc[mi][j][2] + b0, acc[mi][j][3] + b1);
            *(float2*)(Cm + (size_t)row * Nc + col)       = s0;
            *(float2*)(Cm + (size_t)(row + 8) * Nc + col) = s1;
        }
    }
}

// ---------------------------------------------------------------------------
// Landmark projection (SIMT, unchanged)
// ---------------------------------------------------------------------------
__global__ __launch_bounds__(256)
void landmark_kernel(const float* __restrict__ E, const float* __restrict__ qkv,
                     float* __restrict__ klm, float* __restrict__ vlm)
{
    const int bid   = blockIdx.x;
    const int which = bid & 1;
    const int kb    = (bid >> 1) & 3;
    const int bh    = bid >> 3;
    const int b = bh >> 4, h = bh & 15;

    const float* Ea   = E + (h * KL_ + kb * 64) * N_;
    const float* Bsrc = qkv + (size_t)(b * N_) * C3_ + (1 + which) * C_ + h * D_;
    float* outp = (which ? vlm : klm) + (bh * KL_ + kb * 64) * D_;

    __shared__ float AsT[16][68];
    __shared__ float Bs[16][64];

    const int tid = threadIdx.x;
    const int arow = tid >> 2;
    const int ag   = (tid & 3) << 2;
    const int nr   = tid >> 4;
    const int dg   = (tid & 15) << 2;
    const int kr = (tid >> 4) << 2;
    const int dc = (tid & 15) << 2;

    float4 ra = *(const float4*)(Ea + arow * N_ + ag);
    float4 rb = *(const float4*)(Bsrc + (size_t)nr * C3_ + dg);

    float acc[4][4];
#pragma unroll
    for (int i = 0; i < 4; i++)
#pragma unroll
        for (int j = 0; j < 4; j++) acc[i][j] = 0.f;

    for (int n0 = 0; n0 < N_; n0 += 16) {
        __syncthreads();
        AsT[ag + 0][arow] = ra.x;  AsT[ag + 1][arow] = ra.y;
        AsT[ag + 2][arow] = ra.z;  AsT[ag + 3][arow] = ra.w;
        *(float4*)&Bs[nr][dg] = rb;
        __syncthreads();

        if (n0 + 16 < N_) {
            ra = *(const float4*)(Ea + arow * N_ + n0 + 16 + ag);
            rb = *(const float4*)(Bsrc + (size_t)(n0 + 16 + nr) * C3_ + dg);
        }

#pragma unroll
        for (int nn = 0; nn < 16; nn++) {
            float4 a = *(const float4*)&AsT[nn][kr];
            float4 v = *(const float4*)&Bs[nn][dc];
            float avv[4] = {a.x, a.y, a.z, a.w};
            float bvv[4] = {v.x, v.y, v.z, v.w};
#pragma unroll
            for (int i = 0; i < 4; i++)
#pragma unroll
                for (int j = 0; j < 4; j++)
                    acc[i][j] += avv[i] * bvv[j];
        }
    }

#pragma unroll
    for (int i = 0; i < 4; i++) {
        float4 s = make_float4(acc[i][0], acc[i][1], acc[i][2], acc[i][3]);
        *(float4*)&outp[(kr + i) * D_ + dc] = s;
    }
}

// ---------------------------------------------------------------------------
// Fused attention (SIMT, unchanged)
// ---------------------------------------------------------------------------
#define SP_ 264
#define ATTN_SMEM_FLOATS (16384 + 16384 + 2048 + 32 * SP_ + 32)
#define ATTN_SMEM_BYTES  (ATTN_SMEM_FLOATS * 4)

__global__ __launch_bounds__(256)
void attn_kernel(const float* __restrict__ qkv, const float* __restrict__ klm,
                 const float* __restrict__ vlm_g, float* __restrict__ ao)
{
    extern __shared__ float sm[];
    float* klmT = sm;
    float* vlm  = sm + 16384;
    float* qT   = sm + 32768;
    float* sS   = sm + 34816;
    float* rec  = sm + 34816 + 32 * SP_;

    const int bh = blockIdx.x;
    const int b = bh >> 4, h = bh & 15;
    const int tid = threadIdx.x;

    {
        const float* src = klm + (bh * KL_ + tid) * D_;
#pragma unroll
        for (int j = 0; j < 16; j++) {
            float4 v = *(const float4*)(src + j * 4);
            klmT[(j * 4 + 0) * KL_ + tid] = v.x;
            klmT[(j * 4 + 1) * KL_ + tid] = v.y;
            klmT[(j * 4 + 2) * KL_ + tid] = v.z;
            klmT[(j * 4 + 3) * KL_ + tid] = v.w;
        }
        const float4* vsrc = (const float4*)(vlm_g + bh * KL_ * D_);
        float4* vdst = (float4*)vlm;
#pragma unroll
        for (int j = 0; j < 16; j++) vdst[j * 256 + tid] = vsrc[j * 256 + tid];
    }

    const int rg  = (tid >> 5) << 2;
    const int cg  = (tid & 31) << 3;
    const int cg2 = (tid & 31) << 1;
    const int w = tid >> 5, lane = tid & 31;
    const int nb = blockIdx.y * 128;

    for (int t0 = nb; t0 < nb + 128; t0 += 32) {
        {
            const int r = tid & 31, seg = (tid >> 5) << 3;
            const float* qsrc = qkv + (size_t)(b * N_ + t0 + r) * C3_ + h * D_ + seg;
            float4 v0 = *(const float4*)(qsrc);
            float4 v1 = *(const float4*)(qsrc + 4);
            qT[(seg + 0) * 32 + r] = v0.x * 0.125f;
            qT[(seg + 1) * 32 + r] = v0.y * 0.125f;
            qT[(seg + 2) * 32 + r] = v0.z * 0.125f;
            qT[(seg + 3) * 32 + r] = v0.w * 0.125f;
            qT[(seg + 4) * 32 + r] = v1.x * 0.125f;
            qT[(seg + 5) * 32 + r] = v1.y * 0.125f;
            qT[(seg + 6) * 32 + r] = v1.z * 0.125f;
            qT[(seg + 7) * 32 + r] = v1.w * 0.125f;
        }
        __syncthreads();

        float a1[4][8];
#pragma unroll
        for (int i = 0; i < 4; i++)
#pragma unroll
            for (int j = 0; j < 8; j++) a1[i][j] = 0.f;

#pragma unroll 4
        for (int d = 0; d < 64; d++) {
            float4 qv = *(const float4*)&qT[d * 32 + rg];
            float4 k0 = *(const float4*)&klmT[d * KL_ + cg];
            float4 k1 = *(const float4*)&klmT[d * KL_ + cg + 4];
            float qa[4] = {qv.x, qv.y, qv.z, qv.w};
            float kb[8] = {k0.x, k0.y, k0.z, k0.w, k1.x, k1.y, k1.z, k1.w};
#pragma unroll
            for (int i = 0; i < 4; i++)
#pragma unroll
                for (int j = 0; j < 8; j++)
                    a1[i][j] += qa[i] * kb[j];
        }
#pragma unroll
        for (int i = 0; i < 4; i++) {
            *(float4*)&sS[(rg + i) * SP_ + cg] =
                make_float4(a1[i][0], a1[i][1], a1[i][2], a1[i][3]);
            *(float4*)&sS[(rg + i) * SP_ + cg + 4] =
                make_float4(a1[i][4], a1[i][5], a1[i][6], a1[i][7]);
        }
        __syncthreads();

#pragma unroll
        for (int i = 0; i < 4; i++) {
            const int r = w * 4 + i;
            float* row = &sS[r * SP_];
            float v[8];
#pragma unroll
            for (int j = 0; j < 8; j++) v[j] = row[lane + 32 * j];
            float m = v[0];
#pragma unroll
            for (int j = 1; j < 8; j++) m = fmaxf(m, v[j]);
#pragma unroll
            for (int off = 16; off > 0; off >>= 1)
                m = fmaxf(m, __shfl_xor_sync(0xffffffffu, m, off));
            float s = 0.f;
#pragma unroll
            for (int j = 0; j < 8; j++) { v[j] = __expf(v[j] - m); s += v[j]; }
#pragma unroll
            for (int off = 16; off > 0; off >>= 1)
                s += __shfl_xor_sync(0xffffffffu, s, off);
#pragma unroll
            for (int j = 0; j < 8; j++) row[lane + 32 * j] = v[j];
            if (lane == 0) rec[r] = 1.f / s;
        }
        __syncthreads();

        float a2[4][2];
#pragma unroll
        for (int i = 0; i < 4; i++) { a2[i][0] = 0.f; a2[i][1] = 0.f; }

#pragma unroll 2
        for (int k = 0; k < KL_; k += 4) {
            float4 av0 = *(const float4*)&sS[(rg + 0) * SP_ + k];
            float4 av1 = *(const float4*)&sS[(rg + 1) * SP_ + k];
            float4 av2 = *(const float4*)&sS[(rg + 2) * SP_ + k];
            float4 av3 = *(const float4*)&sS[(rg + 3) * SP_ + k];
            float am[4][4] = {{av0.x, av0.y, av0.z, av0.w},
                              {av1.x, av1.y, av1.z, av1.w},
                              {av2.x, av2.y, av2.z, av2.w},
                              {av3.x, av3.y, av3.z, av3.w}};
#pragma unroll
            for (int kk = 0; kk < 4; kk++) {
                float2 vv = *(const float2*)&vlm[(k + kk) * D_ + cg2];
#pragma unroll
                for (int i = 0; i < 4; i++) {
                    a2[i][0] += am[i][kk] * vv.x;
                    a2[i][1] += am[i][kk] * vv.y;
                }
            }
        }

        float* outp = ao + (size_t)(bh * N_ + t0 + rg) * D_ + cg2;
#pragma unroll
        for (int i = 0; i < 4; i++) {
            float rc = rec[rg + i];
            float2 st = make_float2(a2[i][0] * rc, a2[i][1] * rc);
            *(float2*)(outp + i * D_) = st;
        }
        __syncthreads();
    }
}

// ---------------------------------------------------------------------------
extern "C" void kernel_launch(void* const* d_in, const int* in_sizes, int n_in,
                              void* d_out, int out_size)
{
    (void)in_sizes; (void)n_in; (void)out_size;
    const float* x     = (const float*)d_in[0];
    const float* Wqkv  = (const float*)d_in[1];
    const float* E     = (const float*)d_in[2];
    const float* Wproj = (const float*)d_in[3];
    const float* bproj = (const float*)d_in[4];
    float* out = (float*)d_out;

    void *p_qkv, *p_klm, *p_vlm, *p_ao;
    void *p_xh, *p_xl, *p_w3h, *p_w3l, *p_aoh, *p_aol, *p_wph, *p_wpl;
    cudaGetSymbolAddress(&p_qkv, g_qkv);
    cudaGetSymbolAddress(&p_klm, g_klm);
    cudaGetSymbolAddress(&p_vlm, g_vlm);
    cudaGetSymbolAddress(&p_ao,  g_ao);
    cudaGetSymbolAddress(&p_xh,  g_xh);
    cudaGetSymbolAddress(&p_xl,  g_xl);
    cudaGetSymbolAddress(&p_w3h, g_w3h);
    cudaGetSymbolAddress(&p_w3l, g_w3l);
    cudaGetSymbolAddress(&p_aoh, g_aoh);
    cudaGetSymbolAddress(&p_aol, g_aol);
    cudaGetSymbolAddress(&p_wph, g_wph);
    cudaGetSymbolAddress(&p_wpl, g_wpl);

    float* qkv = (float*)p_qkv;
    float* klm = (float*)p_klm;
    float* vlm = (float*)p_vlm;
    float* ao  = (float*)p_ao;

    cudaFuncSetAttribute(attn_kernel, cudaFuncAttributeMaxDynamicSharedMemorySize,
                         ATTN_SMEM_BYTES);
    cudaFuncSetAttribute(gemm_mma_kernel, cudaFuncAttributeMaxDynamicSharedMemorySize,
                         GSMEM);

    const int XN  = B_ * N_ * C_;   // 16777216
    const int W3N = C3_ * C_;       // 3145728
    const int WPN = C_ * C_;        // 1048576

    split_kernel<<<(XN / 4 + 255) / 256, 256>>>(x, (__nv_bfloat16*)p_xh,
                                                (__nv_bfloat16*)p_xl, XN / 4);
    split_kernel<<<(W3N / 4 + 255) / 256, 256>>>(Wqkv, (__nv_bfloat16*)p_w3h,
                                                 (__nv_bfloat16*)p_w3l, W3N / 4);

    // 1) qkv = x @ Wqkv^T   (HMMA, split bf16)
    gemm_mma_kernel<<<dim3(C3_ / 128, (B_ * N_) / 128), 256, GSMEM>>>(
        (__nv_bfloat16*)p_xh, (__nv_bfloat16*)p_xl,
        (__nv_bfloat16*)p_w3h, (__nv_bfloat16*)p_w3l, qkv, nullptr, C3_);

    // 2) landmark projections
    landmark_kernel<<<512, 256>>>(E, qkv, klm, vlm);

    // 3) fused attention
    attn_kernel<<<dim3(B_ * H_, 32), 256, ATTN_SMEM_BYTES>>>(qkv, klm, vlm, ao);

    split_kernel<<<(XN / 4 + 255) / 256, 256>>>(ao, (__nv_bfloat16*)p_aoh,
                                                (__nv_bfloat16*)p_aol, XN / 4);
    split_kernel<<<(WPN / 4 + 255) / 256, 256>>>(Wproj, (__nv_bfloat16*)p_wph,
                                                 (__nv_bfloat16*)p_wpl, WPN / 4);

    // 4) out = ao @ Wproj^T + bproj   (HMMA, split bf16)
    gemm_mma_kernel<<<dim3(C_ / 128, (B_ * N_) / 128), 256, GSMEM>>>(
        (__nv_bfloat16*)p_aoh, (__nv_bfloat16*)p_aol,
        (__nv_bfloat16*)p_wph, (__nv_bfloat16*)p_wpl, out, bproj, C_);
}

// round 5
// speedup vs baseline: 1.7349x; 1.0717x over previous
#include <cuda_runtime.h>
#include <cuda_bf16.h>
#include <cstdint>
#include <math.h>

#define B_  4
#define N_  4096
#define C_  1024
#define H_  16
#define D_  64
#define KL_ 256
#define C3_ 3072

// fp32 scratch
__device__ float g_qkv[B_ * N_ * C3_];        // [b, n, {q|k|v} h d]
__device__ float g_klm[B_ * H_ * KL_ * D_];
__device__ float g_vlm[B_ * H_ * KL_ * D_];
__device__ float g_ao [B_ * H_ * N_ * D_];    // (B,H,N,d) flat

// split-precision bf16 scratch (hi/lo)
__device__ __nv_bfloat16 g_xh [B_ * N_ * C_];
__device__ __nv_bfloat16 g_xl [B_ * N_ * C_];
__device__ __nv_bfloat16 g_w3h[C3_ * C_];
__device__ __nv_bfloat16 g_w3l[C3_ * C_];
__device__ __nv_bfloat16 g_aoh[B_ * N_ * C_];
__device__ __nv_bfloat16 g_aol[B_ * N_ * C_];
__device__ __nv_bfloat16 g_wph[C_ * C_];
__device__ __nv_bfloat16 g_wpl[C_ * C_];
// landmark operands
__device__ __nv_bfloat16 g_eh [H_ * KL_ * N_];            // E hi  [h,k,n]
__device__ __nv_bfloat16 g_el [H_ * KL_ * N_];            // E lo
__device__ __nv_bfloat16 g_kth[B_ * H_ * D_ * N_];        // K^T hi [bh,d,n]
__device__ __nv_bfloat16 g_ktl[B_ * H_ * D_ * N_];
__device__ __nv_bfloat16 g_vth[B_ * H_ * D_ * N_];
__device__ __nv_bfloat16 g_vtl[B_ * H_ * D_ * N_];

// ---------------------------------------------------------------------------
// helpers
// ---------------------------------------------------------------------------
__device__ __forceinline__ uint32_t smem_u32(const void* p) {
    uint32_t a;
    asm("{ .reg .u64 t; cvta.to.shared.u64 t, %1; cvt.u32.u64 %0, t; }"
        : "=r"(a) : "l"(p));
    return a;
}
__device__ __forceinline__ void cp16(uint32_t dst, const void* src) {
    asm volatile("cp.async.cg.shared.global [%0], [%1], 16;"
                 :: "r"(dst), "l"(src) : "memory");
}
__device__ __forceinline__ void cp_commit() {
    asm volatile("cp.async.commit_group;" ::: "memory");
}
#define CP_WAIT(n) asm volatile("cp.async.wait_group %0;" :: "n"(n) : "memory")

#define MMA16816(d, a, b) \
    asm volatile( \
        "mma.sync.aligned.m16n8k16.row.col.f32.bf16.bf16.f32 " \
        "{%0,%1,%2,%3}, {%4,%5,%6,%7}, {%8,%9}, {%0,%1,%2,%3};" \
        : "+f"((d)[0]), "+f"((d)[1]), "+f"((d)[2]), "+f"((d)[3]) \
        : "r"((a)[0]), "r"((a)[1]), "r"((a)[2]), "r"((a)[3]), \
          "r"((b)[0]), "r"((b)[1]))

// ---------------------------------------------------------------------------
// split fp32 -> (hi, lo) bf16
// ---------------------------------------------------------------------------
__global__ __launch_bounds__(256)
void split_kernel(const float* __restrict__ in, __nv_bfloat16* __restrict__ hi,
                  __nv_bfloat16* __restrict__ lo, int n4)
{
    int i = blockIdx.x * blockDim.x + threadIdx.x;
    if (i >= n4) return;
    float4 v = ((const float4*)in)[i];
    __nv_bfloat16 h0 = __float2bfloat16(v.x);
    __nv_bfloat16 h1 = __float2bfloat16(v.y);
    __nv_bfloat16 h2 = __float2bfloat16(v.z);
    __nv_bfloat16 h3 = __float2bfloat16(v.w);
    __nv_bfloat16 l0 = __float2bfloat16(v.x - __bfloat162float(h0));
    __nv_bfloat16 l1 = __float2bfloat16(v.y - __bfloat162float(h1));
    __nv_bfloat16 l2 = __float2bfloat16(v.z - __bfloat162float(h2));
    __nv_bfloat16 l3 = __float2bfloat16(v.w - __bfloat162float(h3));
    __nv_bfloat162* hp = (__nv_bfloat162*)hi;
    __nv_bfloat162* lp = (__nv_bfloat162*)lo;
    hp[2 * i]     = __halves2bfloat162(h0, h1);
    hp[2 * i + 1] = __halves2bfloat162(h2, h3);
    lp[2 * i]     = __halves2bfloat162(l0, l1);
    lp[2 * i + 1] = __halves2bfloat162(l2, l3);
}

// ---------------------------------------------------------------------------
// K/V transpose-split: qkv[b,n,(1|2),h,d] fp32 -> Kt/Vt[bh][d][n] bf16 hi/lo
// Block: one 64n x 64d tile of one (bh, which). Grid = 64nchunk*64bh*2.
// ---------------------------------------------------------------------------
__global__ __launch_bounds__(256)
void kvsplit_kernel(const float* __restrict__ qkv,
                    __nv_bfloat16* __restrict__ kth, __nv_bfloat16* __restrict__ ktl,
                    __nv_bfloat16* __restrict__ vth, __nv_bfloat16* __restrict__ vtl)
{
    __shared__ float tile[64][68];
    const int bid   = blockIdx.x;
    const int which = bid & 1;            // 0=K, 1=V
    const int bh    = (bid >> 1) & 63;
    const int nc    = bid >> 7;           // 0..63 (n chunk of 64)
    const int b = bh >> 4, h = bh & 15;
    const int tid = threadIdx.x;

    // read 64 rows (n) x 64 cols (d), d contiguous
    {
        const int r = tid >> 2, cgp = (tid & 3) << 2;   // 4 float4-cols per thread
        const float* src = qkv + ((size_t)(b * N_ + nc * 64 + r)) * C3_
                         + (1 + which) * C_ + h * D_;
#pragma unroll
        for (int i = 0; i < 4; i++) {
            float4 v = *(const float4*)(src + (cgp + i) * 4);
            tile[r][(cgp + i) * 4 + 0] = v.x;
            tile[r][(cgp + i) * 4 + 1] = v.y;
            tile[r][(cgp + i) * 4 + 2] = v.z;
            tile[r][(cgp + i) * 4 + 3] = v.w;
        }
    }
    __syncthreads();

    // write rows (d) x 64 n contiguous, as bf16 hi/lo
    __nv_bfloat16* dh = (which ? vth : kth) + ((size_t)bh * D_) * N_;
    __nv_bfloat16* dl = (which ? vtl : ktl) + ((size_t)bh * D_) * N_;
    const int d = tid >> 2, ns = (tid & 3) * 16;       // 16 n per thread
    __nv_bfloat162 oh[8], ol[8];
#pragma unroll
    for (int i = 0; i < 8; i++) {
        float f0 = tile[ns + 2 * i][d];
        float f1 = tile[ns + 2 * i + 1][d];
        __nv_bfloat16 h0 = __float2bfloat16(f0);
        __nv_bfloat16 h1 = __float2bfloat16(f1);
        __nv_bfloat16 l0 = __float2bfloat16(f0 - __bfloat162float(h0));
        __nv_bfloat16 l1 = __float2bfloat16(f1 - __bfloat162float(h1));
        oh[i] = __halves2bfloat162(h0, h1);
        ol[i] = __halves2bfloat162(l0, l1);
    }
    size_t off = (size_t)d * N_ + nc * 64 + ns;
    *(uint4*)(dh + off)     = *(uint4*)&oh[0];
    *(uint4*)(dh + off + 8) = *(uint4*)&oh[4];
    *(uint4*)(dl + off)     = *(uint4*)&ol[0];
    *(uint4*)(dl + off + 8) = *(uint4*)&ol[4];
}

// ---------------------------------------------------------------------------
// mma.sync split-bf16 GEMM: C[M,Nc] = A[M,1024] @ B[Nc,1024]^T (+bias)
// CTA tile 128x128, BK=32, 8 warps (4m x 2n), warp tile 32x64.
// ---------------------------------------------------------------------------
#define GK_    1024
#define BKC_   32
#define NCH_   (GK_ / BKC_)
#define PADK_  40
#define TILEB_ (128 * PADK_ * 2)
#define STGB_  (4 * TILEB_)
#define GSMEM  (2 * STGB_)

__device__ __forceinline__ void load_stage(
    uint32_t sb, const __nv_bfloat16* __restrict__ Ah, const __nv_bfloat16* __restrict__ Al,
    const __nv_bfloat16* __restrict__ Bh, const __nv_bfloat16* __restrict__ Bl,
    int m0, int n0, int kof, int tid)
{
    const int r  = tid >> 1;
    const int hf = tid & 1;
    const uint32_t so = (uint32_t)r * (PADK_ * 2) + hf * 32;
    const size_t gA = (size_t)(m0 + r) * GK_ + kof + hf * 16;
    const size_t gB = (size_t)(n0 + r) * GK_ + kof + hf * 16;
    cp16(sb + 0 * TILEB_ + so,      Ah + gA);
    cp16(sb + 0 * TILEB_ + so + 16, Ah + gA + 8);
    cp16(sb + 1 * TILEB_ + so,      Al + gA);
    cp16(sb + 1 * TILEB_ + so + 16, Al + gA + 8);
    cp16(sb + 2 * TILEB_ + so,      Bh + gB);
    cp16(sb + 2 * TILEB_ + so + 16, Bh + gB + 8);
    cp16(sb + 3 * TILEB_ + so,      Bl + gB);
    cp16(sb + 3 * TILEB_ + so + 16, Bl + gB + 8);
}

__global__ __launch_bounds__(256)
void gemm_mma_kernel(const __nv_bfloat16* __restrict__ Ah, const __nv_bfloat16* __restrict__ Al,
                     const __nv_bfloat16* __restrict__ Bh, const __nv_bfloat16* __restrict__ Bl,
                     float* __restrict__ Cm, const float* __restrict__ bias, int Nc)
{
    extern __shared__ __align__(16) char dyn[];
    const uint32_t sbase = smem_u32(dyn);

    const int tid  = threadIdx.x;
    const int warp = tid >> 5, lane = tid & 31;
    const int wm   = warp & 3;
    const int wn   = warp >> 2;
    const int gid  = lane >> 2;
    const int tig  = lane & 3;
    const int m0 = blockIdx.y * 128;
    const int n0 = blockIdx.x * 128;

    float acc[2][8][4];
#pragma unroll
    for (int mi = 0; mi < 2; mi++)
#pragma unroll
        for (int j = 0; j < 8; j++)
#pragma unroll
            for (int q = 0; q < 4; q++) acc[mi][j][q] = 0.f;

    load_stage(sbase, Ah, Al, Bh, Bl, m0, n0, 0, tid);
    cp_commit();

    for (int c = 0; c < NCH_; c++) {
        const int st = c & 1;
        if (c + 1 < NCH_) {
            load_stage(sbase + (st ^ 1) * STGB_, Ah, Al, Bh, Bl, m0, n0,
                       (c + 1) * BKC_, tid);
            cp_commit();
            CP_WAIT(1);
        } else {
            CP_WAIT(0);
        }
        __syncthreads();

        const __nv_bfloat16* sA  = (const __nv_bfloat16*)(dyn + st * STGB_);
        const __nv_bfloat16* sAl = (const __nv_bfloat16*)(dyn + st * STGB_ + TILEB_);
        const __nv_bfloat16* sB  = (const __nv_bfloat16*)(dyn + st * STGB_ + 2 * TILEB_);
        const __nv_bfloat16* sBl = (const __nv_bfloat16*)(dyn + st * STGB_ + 3 * TILEB_);

#pragma unroll
        for (int kk = 0; kk < BKC_; kk += 16) {
            uint32_t rbh[8][2], rbl[8][2];
#pragma unroll
            for (int j = 0; j < 8; j++) {
                const int rb = wn * 64 + j * 8 + gid;
                rbh[j][0] = *(const uint32_t*)&sB [rb * PADK_ + kk + 2 * tig];
                rbh[j][1] = *(const uint32_t*)&sB [rb * PADK_ + kk + 2 * tig + 8];
                rbl[j][0] = *(const uint32_t*)&sBl[rb * PADK_ + kk + 2 * tig];
                rbl[j][1] = *(const uint32_t*)&sBl[rb * PADK_ + kk + 2 * tig + 8];
            }
            uint32_t ra[2][4];
#pragma unroll
            for (int mi = 0; mi < 2; mi++) {
                const int rr = wm * 32 + mi * 16 + gid;
                ra[mi][0] = *(const uint32_t*)&sA[rr * PADK_ + kk + 2 * tig];
                ra[mi][1] = *(const uint32_t*)&sA[(rr + 8) * PADK_ + kk + 2 * tig];
                ra[mi][2] = *(const uint32_t*)&sA[rr * PADK_ + kk + 2 * tig + 8];
                ra[mi][3] = *(const uint32_t*)&sA[(rr + 8) * PADK_ + kk + 2 * tig + 8];
            }
#pragma unroll
            for (int mi = 0; mi < 2; mi++)
#pragma unroll
                for (int j = 0; j < 8; j++) {
                    MMA16816(acc[mi][j], ra[mi], rbh[j]);
                    MMA16816(acc[mi][j], ra[mi], rbl[j]);
                }
#pragma unroll
            for (int mi = 0; mi < 2; mi++) {
                const int rr = wm * 32 + mi * 16 + gid;
                ra[mi][0] = *(const uint32_t*)&sAl[rr * PADK_ + kk + 2 * tig];
                ra[mi][1] = *(const uint32_t*)&sAl[(rr + 8) * PADK_ + kk + 2 * tig];
                ra[mi][2] = *(const uint32_t*)&sAl[rr * PADK_ + kk + 2 * tig + 8];
                ra[mi][3] = *(const uint32_t*)&sAl[(rr + 8) * PADK_ + kk + 2 * tig + 8];
            }
#pragma unroll
            for (int mi = 0; mi < 2; mi++)
#pragma unroll
                for (int j = 0; j < 8; j++)
                    MMA16816(acc[mi][j], ra[mi], rbh[j]);
        }
        __syncthreads();
    }

#pragma unroll
    for (int mi = 0; mi < 2; mi++) {
        const int row = m0 + wm * 32 + mi * 16 + gid;
#pragma unroll
        for (int j = 0; j < 8; j++) {
            const int col = n0 + wn * 64 + j * 8 + 2 * tig;
            float b0 = 0.f, b1 = 0.f;
            if (bias) { b0 = __ldg(bias + col); b1 = __ldg(bias + col + 1); }
            float2 s0 = make_float2(acc[mi][j][0] + b0, acc[mi][j][1] + b1);
            float2 s1 = make_float2(acc[mi][j][2] + b0, acc[mi][j][3] + b1);
            *(float2*)(Cm + (size_t)row * Nc + col)       = s0;
            *(float2*)(Cm + (size_t)(row + 8) * Nc + col) = s1;
        }
    }
}

// ---------------------------------------------------------------------------
// Landmark MMA: per CTA (bh, which): C[256,64] = E[h](256x4096) @ Kt(64x4096)^T
// BK=32 double-buffered, 8 warps (4m x 2n), warp tile 64x32, split-bf16 3-term.
// ---------------------------------------------------------------------------
#define LK_    4096
#define LBK_   32
#define LPAD_  40
#define LA_B   (256 * LPAD_ * 2)     // 20480 B per A matrix
#define LB_B   (64 * LPAD_ * 2)      // 5120 B per B matrix
#define LSTG_  (2 * LA_B + 2 * LB_B) // 51200 B
#define LSMEM  (2 * LSTG_)           // 102400 B

__device__ __forceinline__ void lm_load_stage(
    uint32_t sb, const __nv_bfloat16* __restrict__ Ah, const __nv_bfloat16* __restrict__ Al,
    const __nv_bfloat16* __restrict__ Bh, const __nv_bfloat16* __restrict__ Bl,
    int kof, int tid)
{
    // A: 256 rows x 32 elems (64B) -> thread t loads row t (4 cp16 each matrix)
    {
        const size_t g = (size_t)tid * LK_ + kof;
        const uint32_t so = (uint32_t)tid * (LPAD_ * 2);
#pragma unroll
        for (int j = 0; j < 4; j++) {
            cp16(sb + so + j * 16,        Ah + g + j * 8);
            cp16(sb + LA_B + so + j * 16, Al + g + j * 8);
        }
    }
    // B: 64 rows; threads 0..127 -> hi (2/thread), 128..255 -> lo
    {
        const int t = tid & 127;
        const int r = t >> 1, hf = t & 1;
        const size_t g = (size_t)r * LK_ + kof + hf * 16;
        const uint32_t so = (uint32_t)r * (LPAD_ * 2) + hf * 32;
        const uint32_t base = sb + 2 * LA_B + (tid >> 7) * LB_B;
        const __nv_bfloat16* src = (tid < 128) ? Bh : Bl;
        cp16(base + so,      src + g);
        cp16(base + so + 16, src + g + 8);
    }
}

__global__ __launch_bounds__(256)
void landmark_mma_kernel(const __nv_bfloat16* __restrict__ Eh, const __nv_bfloat16* __restrict__ El,
                         const __nv_bfloat16* __restrict__ kth, const __nv_bfloat16* __restrict__ ktl,
                         const __nv_bfloat16* __restrict__ vth, const __nv_bfloat16* __restrict__ vtl,
                         float* __restrict__ klm, float* __restrict__ vlm)
{
    extern __shared__ __align__(16) char dyn[];
    const uint32_t sbase = smem_u32(dyn);

    const int bid   = blockIdx.x;
    const int which = bid & 1;
    const int bh    = bid >> 1;
    const int h     = bh & 15;

    const __nv_bfloat16* Ah = Eh + (size_t)h * KL_ * LK_;
    const __nv_bfloat16* Al = El + (size_t)h * KL_ * LK_;
    const __nv_bfloat16* Bh = (which ? vth : kth) + (size_t)bh * D_ * LK_;
    const __nv_bfloat16* Bl = (which ? vtl : ktl) + (size_t)bh * D_ * LK_;
    float* outp = (which ? vlm : klm) + (size_t)bh * KL_ * D_;

    const int tid  = threadIdx.x;
    const int warp = tid >> 5, lane = tid & 31;
    const int wm   = warp & 3;        // m base = wm*64
    const int wn   = warp >> 2;       // n base = wn*32
    const int gid  = lane >> 2;
    const int tig  = lane & 3;

    float acc[4][4][4];
#pragma unroll
    for (int mi = 0; mi < 4; mi++)
#pragma unroll
        for (int j = 0; j < 4; j++)
#pragma unroll
            for (int q = 0; q < 4; q++) acc[mi][j][q] = 0.f;

    lm_load_stage(sbase, Ah, Al, Bh, Bl, 0, tid);
    cp_commit();

    for (int c = 0; c < LK_ / LBK_; c++) {
        const int st = c & 1;
        if (c + 1 < LK_ / LBK_) {
            lm_load_stage(sbase + (st ^ 1) * LSTG_, Ah, Al, Bh, Bl,
                          (c + 1) * LBK_, tid);
            cp_commit();
            CP_WAIT(1);
        } else {
            CP_WAIT(0);
        }
        __syncthreads();

        const __nv_bfloat16* sA  = (const __nv_bfloat16*)(dyn + st * LSTG_);
        const __nv_bfloat16* sAl = (const __nv_bfloat16*)(dyn + st * LSTG_ + LA_B);
        const __nv_bfloat16* sB  = (const __nv_bfloat16*)(dyn + st * LSTG_ + 2 * LA_B);
        const __nv_bfloat16* sBl = (const __nv_bfloat16*)(dyn + st * LSTG_ + 2 * LA_B + LB_B);

#pragma unroll
        for (int kk = 0; kk < LBK_; kk += 16) {
            uint32_t rbh[4][2], rbl[4][2];
#pragma unroll
            for (int j = 0; j < 4; j++) {
                const int rb = wn * 32 + j * 8 + gid;
                rbh[j][0] = *(const uint32_t*)&sB [rb * LPAD_ + kk + 2 * tig];
                rbh[j][1] = *(const uint32_t*)&sB [rb * LPAD_ + kk + 2 * tig + 8];
                rbl[j][0] = *(const uint32_t*)&sBl[rb * LPAD_ + kk + 2 * tig];
                rbl[j][1] = *(const uint32_t*)&sBl[rb * LPAD_ + kk + 2 * tig + 8];
            }
            uint32_t ra[4];
#pragma unroll
            for (int mi = 0; mi < 4; mi++) {
                const int rr = wm * 64 + mi * 16 + gid;
                ra[0] = *(const uint32_t*)&sA[rr * LPAD_ + kk + 2 * tig];
                ra[1] = *(const uint32_t*)&sA[(rr + 8) * LPAD_ + kk + 2 * tig];
                ra[2] = *(const uint32_t*)&sA[rr * LPAD_ + kk + 2 * tig + 8];
                ra[3] = *(const uint32_t*)&sA[(rr + 8) * LPAD_ + kk + 2 * tig + 8];
#pragma unroll
                for (int j = 0; j < 4; j++) {
                    MMA16816(acc[mi][j], ra, rbh[j]);
                    MMA16816(acc[mi][j], ra, rbl[j]);
                }
                ra[0] = *(const uint32_t*)&sAl[rr * LPAD_ + kk + 2 * tig];
                ra[1] = *(const uint32_t*)&sAl[(rr + 8) * LPAD_ + kk + 2 * tig];
                ra[2] = *(const uint32_t*)&sAl[rr * LPAD_ + kk + 2 * tig + 8];
                ra[3] = *(const uint32_t*)&sAl[(rr + 8) * LPAD_ + kk + 2 * tig + 8];
#pragma unroll
                for (int j = 0; j < 4; j++)
                    MMA16816(acc[mi][j], ra, rbh[j]);
            }
        }
        __syncthreads();
    }

#pragma unroll
    for (int mi = 0; mi < 4; mi++) {
        const int row = wm * 64 + mi * 16 + gid;
#pragma unroll
        for (int j = 0; j < 4; j++) {
            const int col = wn * 32 + j * 8 + 2 * tig;
            *(float2*)(outp + (size_t)row * D_ + col) =
                make_float2(acc[mi][j][0], acc[mi][j][1]);
            *(float2*)(outp + (size_t)(row + 8) * D_ + col) =
                make_float2(acc[mi][j][2], acc[mi][j][3]);
        }
    }
}

// ---------------------------------------------------------------------------
// Fused attention (SIMT, unchanged)
// ---------------------------------------------------------------------------
#define SP_ 264
#define ATTN_SMEM_FLOATS (16384 + 16384 + 2048 + 32 * SP_ + 32)
#define ATTN_SMEM_BYTES  (ATTN_SMEM_FLOATS * 4)

__global__ __launch_bounds__(256)
void attn_kernel(const float* __restrict__ qkv, const float* __restrict__ klm,
                 const float* __restrict__ vlm_g, float* __restrict__ ao)
{
    extern __shared__ float sm[];
    float* klmT = sm;
    float* vlm  = sm + 16384;
    float* qT   = sm + 32768;
    float* sS   = sm + 34816;
    float* rec  = sm + 34816 + 32 * SP_;

    const int bh = blockIdx.x;
    const int b = bh >> 4, h = bh & 15;
    const int tid = threadIdx.x;

    {
        const float* src = klm + (bh * KL_ + tid) * D_;
#pragma unroll
        for (int j = 0; j < 16; j++) {
            float4 v = *(const float4*)(src + j * 4);
            klmT[(j * 4 + 0) * KL_ + tid] = v.x;
            klmT[(j * 4 + 1) * KL_ + tid] = v.y;
            klmT[(j * 4 + 2) * KL_ + tid] = v.z;
            klmT[(j * 4 + 3) * KL_ + tid] = v.w;
        }
        const float4* vsrc = (const float4*)(vlm_g + bh * KL_ * D_);
        float4* vdst = (float4*)vlm;
#pragma unroll
        for (int j = 0; j < 16; j++) vdst[j * 256 + tid] = vsrc[j * 256 + tid];
    }

    const int rg  = (tid >> 5) << 2;
    const int cg  = (tid & 31) << 3;
    const int cg2 = (tid & 31) << 1;
    const int w = tid >> 5, lane = tid & 31;
    const int nb = blockIdx.y * 128;

    for (int t0 = nb; t0 < nb + 128; t0 += 32) {
        {
            const int r = tid & 31, seg = (tid >> 5) << 3;
            const float* qsrc = qkv + (size_t)(b * N_ + t0 + r) * C3_ + h * D_ + seg;
            float4 v0 = *(const float4*)(qsrc);
            float4 v1 = *(const float4*)(qsrc + 4);
            qT[(seg + 0) * 32 + r] = v0.x * 0.125f;
            qT[(seg + 1) * 32 + r] = v0.y * 0.125f;
            qT[(seg + 2) * 32 + r] = v0.z * 0.125f;
            qT[(seg + 3) * 32 + r] = v0.w * 0.125f;
            qT[(seg + 4) * 32 + r] = v1.x * 0.125f;
            qT[(seg + 5) * 32 + r] = v1.y * 0.125f;
            qT[(seg + 6) * 32 + r] = v1.z * 0.125f;
            qT[(seg + 7) * 32 + r] = v1.w * 0.125f;
        }
        __syncthreads();

        float a1[4][8];
#pragma unroll
        for (int i = 0; i < 4; i++)
#pragma unroll
            for (int j = 0; j < 8; j++) a1[i][j] = 0.f;

#pragma unroll 4
        for (int d = 0; d < 64; d++) {
            float4 qv = *(const float4*)&qT[d * 32 + rg];
            float4 k0 = *(const float4*)&klmT[d * KL_ + cg];
            float4 k1 = *(const float4*)&klmT[d * KL_ + cg + 4];
            float qa[4] = {qv.x, qv.y, qv.z, qv.w};
            float kb[8] = {k0.x, k0.y, k0.z, k0.w, k1.x, k1.y, k1.z, k1.w};
#pragma unroll
            for (int i = 0; i < 4; i++)
#pragma unroll
                for (int j = 0; j < 8; j++)
                    a1[i][j] += qa[i] * kb[j];
        }
#pragma unroll
        for (int i = 0; i < 4; i++) {
            *(float4*)&sS[(rg + i) * SP_ + cg] =
                make_float4(a1[i][0], a1[i][1], a1[i][2], a1[i][3]);
            *(float4*)&sS[(rg + i) * SP_ + cg + 4] =
                make_float4(a1[i][4], a1[i][5], a1[i][6], a1[i][7]);
        }
        __syncthreads();

#pragma unroll
        for (int i = 0; i < 4; i++) {
            const int r = w * 4 + i;
            float* row = &sS[r * SP_];
            float v[8];
#pragma unroll
            for (int j = 0; j < 8; j++) v[j] = row[lane + 32 * j];
            float m = v[0];
#pragma unroll
            for (int j = 1; j < 8; j++) m = fmaxf(m, v[j]);
#pragma unroll
            for (int off = 16; off > 0; off >>= 1)
                m = fmaxf(m, __shfl_xor_sync(0xffffffffu, m, off));
            float s = 0.f;
#pragma unroll
            for (int j = 0; j < 8; j++) { v[j] = __expf(v[j] - m); s += v[j]; }
#pragma unroll
            for (int off = 16; off > 0; off >>= 1)
                s += __shfl_xor_sync(0xffffffffu, s, off);
#pragma unroll
            for (int j = 0; j < 8; j++) row[lane + 32 * j] = v[j];
            if (lane == 0) rec[r] = 1.f / s;
        }
        __syncthreads();

        float a2[4][2];
#pragma unroll
        for (int i = 0; i < 4; i++) { a2[i][0] = 0.f; a2[i][1] = 0.f; }

#pragma unroll 2
        for (int k = 0; k < KL_; k += 4) {
            float4 av0 = *(const float4*)&sS[(rg + 0) * SP_ + k];
            float4 av1 = *(const float4*)&sS[(rg + 1) * SP_ + k];
            float4 av2 = *(const float4*)&sS[(rg + 2) * SP_ + k];
            float4 av3 = *(const float4*)&sS[(rg + 3) * SP_ + k];
            float am[4][4] = {{av0.x, av0.y, av0.z, av0.w},
                              {av1.x, av1.y, av1.z, av1.w},
                              {av2.x, av2.y, av2.z, av2.w},
                              {av3.x, av3.y, av3.z, av3.w}};
#pragma unroll
            for (int kk = 0; kk < 4; kk++) {
                float2 vv = *(const float2*)&vlm[(k + kk) * D_ + cg2];
#pragma unroll
                for (int i = 0; i < 4; i++) {
                    a2[i][0] += am[i][kk] * vv.x;
                    a2[i][1] += am[i][kk] * vv.y;
                }
            }
        }

        float* outp = ao + (size_t)(bh * N_ + t0 + rg) * D_ + cg2;
#pragma unroll
        for (int i = 0; i < 4; i++) {
            float rc = rec[rg + i];
            float2 st = make_float2(a2[i][0] * rc, a2[i][1] * rc);
            *(float2*)(outp + i * D_) = st;
        }
        __syncthreads();
    }
}

// ---------------------------------------------------------------------------
extern "C" void kernel_launch(void* const* d_in, const int* in_sizes, int n_in,
                              void* d_out, int out_size)
{
    (void)in_sizes; (void)n_in; (void)out_size;
    const float* x     = (const float*)d_in[0];
    const float* Wqkv  = (const float*)d_in[1];
    const float* E     = (const float*)d_in[2];
    const float* Wproj = (const float*)d_in[3];
    const float* bproj = (const float*)d_in[4];
    float* out = (float*)d_out;

    void *p_qkv, *p_klm, *p_vlm, *p_ao;
    void *p_xh, *p_xl, *p_w3h, *p_w3l, *p_aoh, *p_aol, *p_wph, *p_wpl;
    void *p_eh, *p_el, *p_kth, *p_ktl, *p_vth, *p_vtl;
    cudaGetSymbolAddress(&p_qkv, g_qkv);
    cudaGetSymbolAddress(&p_klm, g_klm);
    cudaGetSymbolAddress(&p_vlm, g_vlm);
    cudaGetSymbolAddress(&p_ao,  g_ao);
    cudaGetSymbolAddress(&p_xh,  g_xh);
    cudaGetSymbolAddress(&p_xl,  g_xl);
    cudaGetSymbolAddress(&p_w3h, g_w3h);
    cudaGetSymbolAddress(&p_w3l, g_w3l);
    cudaGetSymbolAddress(&p_aoh, g_aoh);
    cudaGetSymbolAddress(&p_aol, g_aol);
    cudaGetSymbolAddress(&p_wph, g_wph);
    cudaGetSymbolAddress(&p_wpl, g_wpl);
    cudaGetSymbolAddress(&p_eh,  g_eh);
    cudaGetSymbolAddress(&p_el,  g_el);
    cudaGetSymbolAddress(&p_kth, g_kth);
    cudaGetSymbolAddress(&p_ktl, g_ktl);
    cudaGetSymbolAddress(&p_vth, g_vth);
    cudaGetSymbolAddress(&p_vtl, g_vtl);

    float* qkv = (float*)p_qkv;
    float* klm = (float*)p_klm;
    float* vlm = (float*)p_vlm;
    float* ao  = (float*)p_ao;

    cudaFuncSetAttribute(attn_kernel, cudaFuncAttributeMaxDynamicSharedMemorySize,
                         ATTN_SMEM_BYTES);
    cudaFuncSetAttribute(gemm_mma_kernel, cudaFuncAttributeMaxDynamicSharedMemorySize,
                         GSMEM);
    cudaFuncSetAttribute(landmark_mma_kernel, cudaFuncAttributeMaxDynamicSharedMemorySize,
                         LSMEM);

    const int XN  = B_ * N_ * C_;   // 16777216
    const int W3N = C3_ * C_;
    const int WPN = C_ * C_;
    const int EN  = H_ * KL_ * N_;  // 16777216

    split_kernel<<<(XN / 4 + 255) / 256, 256>>>(x, (__nv_bfloat16*)p_xh,
                                                (__nv_bfloat16*)p_xl, XN / 4);
    split_kernel<<<(W3N / 4 + 255) / 256, 256>>>(Wqkv, (__nv_bfloat16*)p_w3h,
                                                 (__nv_bfloat16*)p_w3l, W3N / 4);
    split_kernel<<<(EN / 4 + 255) / 256, 256>>>(E, (__nv_bfloat16*)p_eh,
                                                (__nv_bfloat16*)p_el, EN / 4);

    // 1) qkv = x @ Wqkv^T
    gemm_mma_kernel<<<dim3(C3_ / 128, (B_ * N_) / 128), 256, GSMEM>>>(
        (__nv_bfloat16*)p_xh, (__nv_bfloat16*)p_xl,
        (__nv_bfloat16*)p_w3h, (__nv_bfloat16*)p_w3l, qkv, nullptr, C3_);

    // 2) K/V transpose-split
    kvsplit_kernel<<<64 * 64 * 2, 256>>>(qkv,
        (__nv_bfloat16*)p_kth, (__nv_bfloat16*)p_ktl,
        (__nv_bfloat16*)p_vth, (__nv_bfloat16*)p_vtl);

    // 3) landmark projections via MMA
    landmark_mma_kernel<<<128, 256, LSMEM>>>(
        (__nv_bfloat16*)p_eh, (__nv_bfloat16*)p_el,
        (__nv_bfloat16*)p_kth, (__nv_bfloat16*)p_ktl,
        (__nv_bfloat16*)p_vth, (__nv_bfloat16*)p_vtl, klm, vlm);

    // 4) fused attention
    attn_kernel<<<dim3(B_ * H_, 32), 256, ATTN_SMEM_BYTES>>>(qkv, klm, vlm, ao);

    split_kernel<<<(XN / 4 + 255) / 256, 256>>>(ao, (__nv_bfloat16*)p_aoh,
                                                (__nv_bfloat16*)p_aol, XN / 4);
    split_kernel<<<(WPN / 4 + 255) / 256, 256>>>(Wproj, (__nv_bfloat16*)p_wph,
                                                 (__nv_bfloat16*)p_wpl, WPN / 4);

    // 5) out = ao @ Wproj^T + bproj
    gemm_mma_kernel<<<dim3(C_ / 128, (B_ * N_) / 128), 256, GSMEM>>>(
        (__nv_bfloat16*)p_aoh, (__nv_bfloat16*)p_aol,
        (__nv_bfloat16*)p_wph, (__nv_bfloat16*)p_wpl, out, bproj, C_);
}

// round 6
// speedup vs baseline: 1.7378x; 1.0016x over previous
#include <cuda_runtime.h>
#include <cuda_bf16.h>
#include <cstdint>
#include <math.h>

#define B_  4
#define N_  4096
#define C_  1024
#define H_  16
#define D_  64
#define KL_ 256
#define C3_ 3072

// fp32 scratch
__device__ float g_qkv[B_ * N_ * C3_];        // [b, n, {q|k|v} h d]
__device__ float g_klm[B_ * H_ * KL_ * D_];
__device__ float g_vlm[B_ * H_ * KL_ * D_];
__device__ float g_ao [B_ * H_ * N_ * D_];    // (B,H,N,d) flat

// split-precision bf16 scratch (hi/lo)
__device__ __nv_bfloat16 g_xh [B_ * N_ * C_];
__device__ __nv_bfloat16 g_xl [B_ * N_ * C_];
__device__ __nv_bfloat16 g_w3h[C3_ * C_];
__device__ __nv_bfloat16 g_w3l[C3_ * C_];
__device__ __nv_bfloat16 g_aoh[B_ * N_ * C_];
__device__ __nv_bfloat16 g_aol[B_ * N_ * C_];
__device__ __nv_bfloat16 g_wph[C_ * C_];
__device__ __nv_bfloat16 g_wpl[C_ * C_];
// landmark operands
__device__ __nv_bfloat16 g_eh [H_ * KL_ * N_];            // E hi  [h,k,n]
__device__ __nv_bfloat16 g_el [H_ * KL_ * N_];            // E lo
__device__ __nv_bfloat16 g_kth[B_ * H_ * D_ * N_];        // K^T hi [bh,d,n]
__device__ __nv_bfloat16 g_ktl[B_ * H_ * D_ * N_];
__device__ __nv_bfloat16 g_vth[B_ * H_ * D_ * N_];
__device__ __nv_bfloat16 g_vtl[B_ * H_ * D_ * N_];

// ---------------------------------------------------------------------------
// helpers
// ---------------------------------------------------------------------------
__device__ __forceinline__ uint32_t smem_u32(const void* p) {
    uint32_t a;
    asm("{ .reg .u64 t; cvta.to.shared.u64 t, %1; cvt.u32.u64 %0, t; }"
        : "=r"(a) : "l"(p));
    return a;
}
__device__ __forceinline__ void cp16(uint32_t dst, const void* src) {
    asm volatile("cp.async.cg.shared.global [%0], [%1], 16;"
                 :: "r"(dst), "l"(src) : "memory");
}
__device__ __forceinline__ void cp_commit() {
    asm volatile("cp.async.commit_group;" ::: "memory");
}
#define CP_WAIT(n) asm volatile("cp.async.wait_group %0;" :: "n"(n) : "memory")

#define MMA16816(d, a, b) \
    asm volatile( \
        "mma.sync.aligned.m16n8k16.row.col.f32.bf16.bf16.f32 " \
        "{%0,%1,%2,%3}, {%4,%5,%6,%7}, {%8,%9}, {%0,%1,%2,%3};" \
        : "+f"((d)[0]), "+f"((d)[1]), "+f"((d)[2]), "+f"((d)[3]) \
        : "r"((a)[0]), "r"((a)[1]), "r"((a)[2]), "r"((a)[3]), \
          "r"((b)[0]), "r"((b)[1]))

// ---------------------------------------------------------------------------
// split fp32 -> (hi, lo) bf16
// ---------------------------------------------------------------------------
__global__ __launch_bounds__(256)
void split_kernel(const float* __restrict__ in, __nv_bfloat16* __restrict__ hi,
                  __nv_bfloat16* __restrict__ lo, int n4)
{
    int i = blockIdx.x * blockDim.x + threadIdx.x;
    if (i >= n4) return;
    float4 v = ((const float4*)in)[i];
    __nv_bfloat16 h0 = __float2bfloat16(v.x);
    __nv_bfloat16 h1 = __float2bfloat16(v.y);
    __nv_bfloat16 h2 = __float2bfloat16(v.z);
    __nv_bfloat16 h3 = __float2bfloat16(v.w);
    __nv_bfloat16 l0 = __float2bfloat16(v.x - __bfloat162float(h0));
    __nv_bfloat16 l1 = __float2bfloat16(v.y - __bfloat162float(h1));
    __nv_bfloat16 l2 = __float2bfloat16(v.z - __bfloat162float(h2));
    __nv_bfloat16 l3 = __float2bfloat16(v.w - __bfloat162float(h3));
    __nv_bfloat162* hp = (__nv_bfloat162*)hi;
    __nv_bfloat162* lp = (__nv_bfloat162*)lo;
    hp[2 * i]     = __halves2bfloat162(h0, h1);
    hp[2 * i + 1] = __halves2bfloat162(h2, h3);
    lp[2 * i]     = __halves2bfloat162(l0, l1);
    lp[2 * i + 1] = __halves2bfloat162(l2, l3);
}

// ---------------------------------------------------------------------------
// K/V transpose-split: qkv[b,n,(1|2),h,d] fp32 -> Kt/Vt[bh][d][n] bf16 hi/lo
// ---------------------------------------------------------------------------
__global__ __launch_bounds__(256)
void kvsplit_kernel(const float* __restrict__ qkv,
                    __nv_bfloat16* __restrict__ kth, __nv_bfloat16* __restrict__ ktl,
                    __nv_bfloat16* __restrict__ vth, __nv_bfloat16* __restrict__ vtl)
{
    __shared__ float tile[64][68];
    const int bid   = blockIdx.x;
    const int which = bid & 1;
    const int bh    = (bid >> 1) & 63;
    const int nc    = bid >> 7;
    const int b = bh >> 4, h = bh & 15;
    const int tid = threadIdx.x;

    {
        const int r = tid >> 2, cgp = (tid & 3) << 2;
        const float* src = qkv + ((size_t)(b * N_ + nc * 64 + r)) * C3_
                         + (1 + which) * C_ + h * D_;
#pragma unroll
        for (int i = 0; i < 4; i++) {
            float4 v = *(const float4*)(src + (cgp + i) * 4);
            tile[r][(cgp + i) * 4 + 0] = v.x;
            tile[r][(cgp + i) * 4 + 1] = v.y;
            tile[r][(cgp + i) * 4 + 2] = v.z;
            tile[r][(cgp + i) * 4 + 3] = v.w;
        }
    }
    __syncthreads();

    __nv_bfloat16* dh = (which ? vth : kth) + ((size_t)bh * D_) * N_;
    __nv_bfloat16* dl = (which ? vtl : ktl) + ((size_t)bh * D_) * N_;
    const int d = tid >> 2, ns = (tid & 3) * 16;
    __nv_bfloat162 oh[8], ol[8];
#pragma unroll
    for (int i = 0; i < 8; i++) {
        float f0 = tile[ns + 2 * i][d];
        float f1 = tile[ns + 2 * i + 1][d];
        __nv_bfloat16 h0 = __float2bfloat16(f0);
        __nv_bfloat16 h1 = __float2bfloat16(f1);
        __nv_bfloat16 l0 = __float2bfloat16(f0 - __bfloat162float(h0));
        __nv_bfloat16 l1 = __float2bfloat16(f1 - __bfloat162float(h1));
        oh[i] = __halves2bfloat162(h0, h1);
        ol[i] = __halves2bfloat162(l0, l1);
    }
    size_t off = (size_t)d * N_ + nc * 64 + ns;
    *(uint4*)(dh + off)     = *(uint4*)&oh[0];
    *(uint4*)(dh + off + 8) = *(uint4*)&oh[4];
    *(uint4*)(dl + off)     = *(uint4*)&ol[0];
    *(uint4*)(dl + off + 8) = *(uint4*)&ol[4];
}

// ---------------------------------------------------------------------------
// mma.sync split-bf16 GEMM: C[M,Nc] = A[M,1024] @ B[Nc,1024]^T (+bias)
// CTA tile 128x128, BK=32, 8 warps (4m x 2n), warp tile 32x64.
// Inner loop = 3 separate passes so each accumulator is re-touched only after
// 16 independent MMAs (hides HMMA latency; fixes tensor=51.7% stall).
// ---------------------------------------------------------------------------
#define GK_    1024
#define BKC_   32
#define NCH_   (GK_ / BKC_)
#define PADK_  40
#define TILEB_ (128 * PADK_ * 2)
#define STGB_  (4 * TILEB_)
#define GSMEM  (2 * STGB_)

__device__ __forceinline__ void load_stage(
    uint32_t sb, const __nv_bfloat16* __restrict__ Ah, const __nv_bfloat16* __restrict__ Al,
    const __nv_bfloat16* __restrict__ Bh, const __nv_bfloat16* __restrict__ Bl,
    int m0, int n0, int kof, int tid)
{
    const int r  = tid >> 1;
    const int hf = tid & 1;
    const uint32_t so = (uint32_t)r * (PADK_ * 2) + hf * 32;
    const size_t gA = (size_t)(m0 + r) * GK_ + kof + hf * 16;
    const size_t gB = (size_t)(n0 + r) * GK_ + kof + hf * 16;
    cp16(sb + 0 * TILEB_ + so,      Ah + gA);
    cp16(sb + 0 * TILEB_ + so + 16, Ah + gA + 8);
    cp16(sb + 1 * TILEB_ + so,      Al + gA);
    cp16(sb + 1 * TILEB_ + so + 16, Al + gA + 8);
    cp16(sb + 2 * TILEB_ + so,      Bh + gB);
    cp16(sb + 2 * TILEB_ + so + 16, Bh + gB + 8);
    cp16(sb + 3 * TILEB_ + so,      Bl + gB);
    cp16(sb + 3 * TILEB_ + so + 16, Bl + gB + 8);
}

__global__ __launch_bounds__(256)
void gemm_mma_kernel(const __nv_bfloat16* __restrict__ Ah, const __nv_bfloat16* __restrict__ Al,
                     const __nv_bfloat16* __restrict__ Bh, const __nv_bfloat16* __restrict__ Bl,
                     float* __restrict__ Cm, const float* __restrict__ bias, int Nc)
{
    extern __shared__ __align__(16) char dyn[];
    const uint32_t sbase = smem_u32(dyn);

    const int tid  = threadIdx.x;
    const int warp = tid >> 5, lane = tid & 31;
    const int wm   = warp & 3;
    const int wn   = warp >> 2;
    const int gid  = lane >> 2;
    const int tig  = lane & 3;
    const int m0 = blockIdx.y * 128;
    const int n0 = blockIdx.x * 128;

    float acc[2][8][4];
#pragma unroll
    for (int mi = 0; mi < 2; mi++)
#pragma unroll
        for (int j = 0; j < 8; j++)
#pragma unroll
            for (int q = 0; q < 4; q++) acc[mi][j][q] = 0.f;

    load_stage(sbase, Ah, Al, Bh, Bl, m0, n0, 0, tid);
    cp_commit();

    for (int c = 0; c < NCH_; c++) {
        const int st = c & 1;
        if (c + 1 < NCH_) {
            load_stage(sbase + (st ^ 1) * STGB_, Ah, Al, Bh, Bl, m0, n0,
                       (c + 1) * BKC_, tid);
            cp_commit();
            CP_WAIT(1);
        } else {
            CP_WAIT(0);
        }
        __syncthreads();

        const __nv_bfloat16* sA  = (const __nv_bfloat16*)(dyn + st * STGB_);
        const __nv_bfloat16* sAl = (const __nv_bfloat16*)(dyn + st * STGB_ + TILEB_);
        const __nv_bfloat16* sB  = (const __nv_bfloat16*)(dyn + st * STGB_ + 2 * TILEB_);
        const __nv_bfloat16* sBl = (const __nv_bfloat16*)(dyn + st * STGB_ + 3 * TILEB_);

#pragma unroll
        for (int kk = 0; kk < BKC_; kk += 16) {
            uint32_t rbh[8][2], rbl[8][2];
#pragma unroll
            for (int j = 0; j < 8; j++) {
                const int rb = wn * 64 + j * 8 + gid;
                rbh[j][0] = *(const uint32_t*)&sB [rb * PADK_ + kk + 2 * tig];
                rbh[j][1] = *(const uint32_t*)&sB [rb * PADK_ + kk + 2 * tig + 8];
                rbl[j][0] = *(const uint32_t*)&sBl[rb * PADK_ + kk + 2 * tig];
                rbl[j][1] = *(const uint32_t*)&sBl[rb * PADK_ + kk + 2 * tig + 8];
            }
            uint32_t ra[2][4];
#pragma unroll
            for (int mi = 0; mi < 2; mi++) {
                const int rr = wm * 32 + mi * 16 + gid;
                ra[mi][0] = *(const uint32_t*)&sA[rr * PADK_ + kk + 2 * tig];
                ra[mi][1] = *(const uint32_t*)&sA[(rr + 8) * PADK_ + kk + 2 * tig];
                ra[mi][2] = *(const uint32_t*)&sA[rr * PADK_ + kk + 2 * tig + 8];
                ra[mi][3] = *(const uint32_t*)&sA[(rr + 8) * PADK_ + kk + 2 * tig + 8];
            }
            // pass 1: Ahi * Bhi  (16 independent MMAs)
#pragma unroll
            for (int mi = 0; mi < 2; mi++)
#pragma unroll
                for (int j = 0; j < 8; j++)
                    MMA16816(acc[mi][j], ra[mi], rbh[j]);
            // pass 2: Ahi * Blo  (each acc re-touched after 16 MMAs)
#pragma unroll
            for (int mi = 0; mi < 2; mi++)
#pragma unroll
                for (int j = 0; j < 8; j++)
                    MMA16816(acc[mi][j], ra[mi], rbl[j]);
            // pass 3: Alo * Bhi
#pragma unroll
            for (int mi = 0; mi < 2; mi++) {
                const int rr = wm * 32 + mi * 16 + gid;
                ra[mi][0] = *(const uint32_t*)&sAl[rr * PADK_ + kk + 2 * tig];
                ra[mi][1] = *(const uint32_t*)&sAl[(rr + 8) * PADK_ + kk + 2 * tig];
                ra[mi][2] = *(const uint32_t*)&sAl[rr * PADK_ + kk + 2 * tig + 8];
                ra[mi][3] = *(const uint32_t*)&sAl[(rr + 8) * PADK_ + kk + 2 * tig + 8];
            }
#pragma unroll
            for (int mi = 0; mi < 2; mi++)
#pragma unroll
                for (int j = 0; j < 8; j++)
                    MMA16816(acc[mi][j], ra[mi], rbh[j]);
        }
        __syncthreads();
    }

#pragma unroll
    for (int mi = 0; mi < 2; mi++) {
        const int row = m0 + wm * 32 + mi * 16 + gid;
#pragma unroll
        for (int j = 0; j < 8; j++) {
            const int col = n0 + wn * 64 + j * 8 + 2 * tig;
            float b0 = 0.f, b1 = 0.f;
            if (bias) { b0 = __ldg(bias + col); b1 = __ldg(bias + col + 1); }
            float2 s0 = make_float2(acc[mi][j][0] + b0, acc[mi][j][1] + b1);
            float2 s1 = make_float2(acc[mi][j][2] + b0, acc[mi][j][3] + b1);
            *(float2*)(Cm + (size_t)row * Nc + col)       = s0;
            *(float2*)(Cm + (size_t)(row + 8) * Nc + col) = s1;
        }
    }
}

// ---------------------------------------------------------------------------
// Landmark MMA: per CTA (bh, which): C[256,64] = E[h](256x4096) @ Kt(64x4096)^T
// Same 3-pass restructure.
// ---------------------------------------------------------------------------
#define LK_    4096
#define LBK_   32
#define LPAD_  40
#define LA_B   (256 * LPAD_ * 2)
#define LB_B   (64 * LPAD_ * 2)
#define LSTG_  (2 * LA_B + 2 * LB_B)
#define LSMEM  (2 * LSTG_)

__device__ __forceinline__ void lm_load_stage(
    uint32_t sb, const __nv_bfloat16* __restrict__ Ah, const __nv_bfloat16* __restrict__ Al,
    const __nv_bfloat16* __restrict__ Bh, const __nv_bfloat16* __restrict__ Bl,
    int kof, int tid)
{
    {
        const size_t g = (size_t)tid * LK_ + kof;
        const uint32_t so = (uint32_t)tid * (LPAD_ * 2);
#pragma unroll
        for (int j = 0; j < 4; j++) {
            cp16(sb + so + j * 16,        Ah + g + j * 8);
            cp16(sb + LA_B + so + j * 16, Al + g + j * 8);
        }
    }
    {
        const int t = tid & 127;
        const int r = t >> 1, hf = t & 1;
        const size_t g = (size_t)r * LK_ + kof + hf * 16;
        const uint32_t so = (uint32_t)r * (LPAD_ * 2) + hf * 32;
        const uint32_t base = sb + 2 * LA_B + (tid >> 7) * LB_B;
        const __nv_bfloat16* src = (tid < 128) ? Bh : Bl;
        cp16(base + so,      src + g);
        cp16(base + so + 16, src + g + 8);
    }
}

__global__ __launch_bounds__(256)
void landmark_mma_kernel(const __nv_bfloat16* __restrict__ Eh, const __nv_bfloat16* __restrict__ El,
                         const __nv_bfloat16* __restrict__ kth, const __nv_bfloat16* __restrict__ ktl,
                         const __nv_bfloat16* __restrict__ vth, const __nv_bfloat16* __restrict__ vtl,
                         float* __restrict__ klm, float* __restrict__ vlm)
{
    extern __shared__ __align__(16) char dyn[];
    const uint32_t sbase = smem_u32(dyn);

    const int bid   = blockIdx.x;
    const int which = bid & 1;
    const int bh    = bid >> 1;
    const int h     = bh & 15;

    const __nv_bfloat16* Ah = Eh + (size_t)h * KL_ * LK_;
    const __nv_bfloat16* Al = El + (size_t)h * KL_ * LK_;
    const __nv_bfloat16* Bh = (which ? vth : kth) + (size_t)bh * D_ * LK_;
    const __nv_bfloat16* Bl = (which ? vtl : ktl) + (size_t)bh * D_ * LK_;
    float* outp = (which ? vlm : klm) + (size_t)bh * KL_ * D_;

    const int tid  = threadIdx.x;
    const int warp = tid >> 5, lane = tid & 31;
    const int wm   = warp & 3;
    const int wn   = warp >> 2;
    const int gid  = lane >> 2;
    const int tig  = lane & 3;

    float acc[4][4][4];
#pragma unroll
    for (int mi = 0; mi < 4; mi++)
#pragma unroll
        for (int j = 0; j < 4; j++)
#pragma unroll
            for (int q = 0; q < 4; q++) acc[mi][j][q] = 0.f;

    lm_load_stage(sbase, Ah, Al, Bh, Bl, 0, tid);
    cp_commit();

    for (int c = 0; c < LK_ / LBK_; c++) {
        const int st = c & 1;
        if (c + 1 < LK_ / LBK_) {
            lm_load_stage(sbase + (st ^ 1) * LSTG_, Ah, Al, Bh, Bl,
                          (c + 1) * LBK_, tid);
            cp_commit();
            CP_WAIT(1);
        } else {
            CP_WAIT(0);
        }
        __syncthreads();

        const __nv_bfloat16* sA  = (const __nv_bfloat16*)(dyn + st * LSTG_);
        const __nv_bfloat16* sAl = (const __nv_bfloat16*)(dyn + st * LSTG_ + LA_B);
        const __nv_bfloat16* sB  = (const __nv_bfloat16*)(dyn + st * LSTG_ + 2 * LA_B);
        const __nv_bfloat16* sBl = (const __nv_bfloat16*)(dyn + st * LSTG_ + 2 * LA_B + LB_B);

#pragma unroll
        for (int kk = 0; kk < LBK_; kk += 16) {
            uint32_t rbh[4][2], rbl[4][2];
#pragma unroll
            for (int j = 0; j < 4; j++) {
                const int rb = wn * 32 + j * 8 + gid;
                rbh[j][0] = *(const uint32_t*)&sB [rb * LPAD_ + kk + 2 * tig];
                rbh[j][1] = *(const uint32_t*)&sB [rb * LPAD_ + kk + 2 * tig + 8];
                rbl[j][0] = *(const uint32_t*)&sBl[rb * LPAD_ + kk + 2 * tig];
                rbl[j][1] = *(const uint32_t*)&sBl[rb * LPAD_ + kk + 2 * tig + 8];
            }
            uint32_t ra[4][4];
#pragma unroll
            for (int mi = 0; mi < 4; mi++) {
                const int rr = wm * 64 + mi * 16 + gid;
                ra[mi][0] = *(const uint32_t*)&sA[rr * LPAD_ + kk + 2 * tig];
                ra[mi][1] = *(const uint32_t*)&sA[(rr + 8) * LPAD_ + kk + 2 * tig];
                ra[mi][2] = *(const uint32_t*)&sA[rr * LPAD_ + kk + 2 * tig + 8];
                ra[mi][3] = *(const uint32_t*)&sA[(rr + 8) * LPAD_ + kk + 2 * tig + 8];
            }
            // pass 1: Ehi * Bhi
#pragma unroll
            for (int mi = 0; mi < 4; mi++)
#pragma unroll
                for (int j = 0; j < 4; j++)
                    MMA16816(acc[mi][j], ra[mi], rbh[j]);
            // pass 2: Ehi * Blo
#pragma unroll
            for (int mi = 0; mi < 4; mi++)
#pragma unroll
                for (int j = 0; j < 4; j++)
                    MMA16816(acc[mi][j], ra[mi], rbl[j]);
            // pass 3: Elo * Bhi
#pragma unroll
            for (int mi = 0; mi < 4; mi++) {
                const int rr = wm * 64 + mi * 16 + gid;
                ra[mi][0] = *(const uint32_t*)&sAl[rr * LPAD_ + kk + 2 * tig];
                ra[mi][1] = *(const uint32_t*)&sAl[(rr + 8) * LPAD_ + kk + 2 * tig];
                ra[mi][2] = *(const uint32_t*)&sAl[rr * LPAD_ + kk + 2 * tig + 8];
                ra[mi][3] = *(const uint32_t*)&sAl[(rr + 8) * LPAD_ + kk + 2 * tig + 8];
            }
#pragma unroll
            for (int mi = 0; mi < 4; mi++)
#pragma unroll
                for (int j = 0; j < 4; j++)
                    MMA16816(acc[mi][j], ra[mi], rbh[j]);
        }
        __syncthreads();
    }

#pragma unroll
    for (int mi = 0; mi < 4; mi++) {
        const int row = wm * 64 + mi * 16 + gid;
#pragma unroll
        for (int j = 0; j < 4; j++) {
            const int col = wn * 32 + j * 8 + 2 * tig;
            *(float2*)(outp + (size_t)row * D_ + col) =
                make_float2(acc[mi][j][0], acc[mi][j][1]);
            *(float2*)(outp + (size_t)(row + 8) * D_ + col) =
                make_float2(acc[mi][j][2], acc[mi][j][3]);
        }
    }
}

// ---------------------------------------------------------------------------
// Fused attention (SIMT, unchanged)
// ---------------------------------------------------------------------------
#define SP_ 264
#define ATTN_SMEM_FLOATS (16384 + 16384 + 2048 + 32 * SP_ + 32)
#define ATTN_SMEM_BYTES  (ATTN_SMEM_FLOATS * 4)

__global__ __launch_bounds__(256)
void attn_kernel(const float* __restrict__ qkv, const float* __restrict__ klm,
                 const float* __restrict__ vlm_g, float* __restrict__ ao)
{
    extern __shared__ float sm[];
    float* klmT = sm;
    float* vlm  = sm + 16384;
    float* qT   = sm + 32768;
    float* sS   = sm + 34816;
    float* rec  = sm + 34816 + 32 * SP_;

    const int bh = blockIdx.x;
    const int b = bh >> 4, h = bh & 15;
    const int tid = threadIdx.x;

    {
        const float* src = klm + (bh * KL_ + tid) * D_;
#pragma unroll
        for (int j = 0; j < 16; j++) {
            float4 v = *(const float4*)(src + j * 4);
            klmT[(j * 4 + 0) * KL_ + tid] = v.x;
            klmT[(j * 4 + 1) * KL_ + tid] = v.y;
            klmT[(j * 4 + 2) * KL_ + tid] = v.z;
            klmT[(j * 4 + 3) * KL_ + tid] = v.w;
        }
        const float4* vsrc = (const float4*)(vlm_g + bh * KL_ * D_);
        float4* vdst = (float4*)vlm;
#pragma unroll
        for (int j = 0; j < 16; j++) vdst[j * 256 + tid] = vsrc[j * 256 + tid];
    }

    const int rg  = (tid >> 5) << 2;
    const int cg  = (tid & 31) << 3;
    const int cg2 = (tid & 31) << 1;
    const int w = tid >> 5, lane = tid & 31;
    const int nb = blockIdx.y * 128;

    for (int t0 = nb; t0 < nb + 128; t0 += 32) {
        {
            const int r = tid & 31, seg = (tid >> 5) << 3;
            const float* qsrc = qkv + (size_t)(b * N_ + t0 + r) * C3_ + h * D_ + seg;
            float4 v0 = *(const float4*)(qsrc);
            float4 v1 = *(const float4*)(qsrc + 4);
            qT[(seg + 0) * 32 + r] = v0.x * 0.125f;
            qT[(seg + 1) * 32 + r] = v0.y * 0.125f;
            qT[(seg + 2) * 32 + r] = v0.z * 0.125f;
            qT[(seg + 3) * 32 + r] = v0.w * 0.125f;
            qT[(seg + 4) * 32 + r] = v1.x * 0.125f;
            qT[(seg + 5) * 32 + r] = v1.y * 0.125f;
            qT[(seg + 6) * 32 + r] = v1.z * 0.125f;
            qT[(seg + 7) * 32 + r] = v1.w * 0.125f;
        }
        __syncthreads();

        float a1[4][8];
#pragma unroll
        for (int i = 0; i < 4; i++)
#pragma unroll
            for (int j = 0; j < 8; j++) a1[i][j] = 0.f;

#pragma unroll 4
        for (int d = 0; d < 64; d++) {
            float4 qv = *(const float4*)&qT[d * 32 + rg];
            float4 k0 = *(const float4*)&klmT[d * KL_ + cg];
            float4 k1 = *(const float4*)&klmT[d * KL_ + cg + 4];
            float qa[4] = {qv.x, qv.y, qv.z, qv.w};
            float kb[8] = {k0.x, k0.y, k0.z, k0.w, k1.x, k1.y, k1.z, k1.w};
#pragma unroll
            for (int i = 0; i < 4; i++)
#pragma unroll
                for (int j = 0; j < 8; j++)
                    a1[i][j] += qa[i] * kb[j];
        }
#pragma unroll
        for (int i = 0; i < 4; i++) {
            *(float4*)&sS[(rg + i) * SP_ + cg] =
                make_float4(a1[i][0], a1[i][1], a1[i][2], a1[i][3]);
            *(float4*)&sS[(rg + i) * SP_ + cg + 4] =
                make_float4(a1[i][4], a1[i][5], a1[i][6], a1[i][7]);
        }
        __syncthreads();

#pragma unroll
        for (int i = 0; i < 4; i++) {
            const int r = w * 4 + i;
            float* row = &sS[r * SP_];
            float v[8];
#pragma unroll
            for (int j = 0; j < 8; j++) v[j] = row[lane + 32 * j];
            float m = v[0];
#pragma unroll
            for (int j = 1; j < 8; j++) m = fmaxf(m, v[j]);
#pragma unroll
            for (int off = 16; off > 0; off >>= 1)
                m = fmaxf(m, __shfl_xor_sync(0xffffffffu, m, off));
            float s = 0.f;
#pragma unroll
            for (int j = 0; j < 8; j++) { v[j] = __expf(v[j] - m); s += v[j]; }
#pragma unroll
            for (int off = 16; off > 0; off >>= 1)
                s += __shfl_xor_sync(0xffffffffu, s, off);
#pragma unroll
            for (int j = 0; j < 8; j++) row[lane + 32 * j] = v[j];
            if (lane == 0) rec[r] = 1.f / s;
        }
        __syncthreads();

        float a2[4][2];
#pragma unroll
        for (int i = 0; i < 4; i++) { a2[i][0] = 0.f; a2[i][1] = 0.f; }

#pragma unroll 2
        for (int k = 0; k < KL_; k += 4) {
            float4 av0 = *(const float4*)&sS[(rg + 0) * SP_ + k];
            float4 av1 = *(const float4*)&sS[(rg + 1) * SP_ + k];
            float4 av2 = *(const float4*)&sS[(rg + 2) * SP_ + k];
            float4 av3 = *(const float4*)&sS[(rg + 3) * SP_ + k];
            float am[4][4] = {{av0.x, av0.y, av0.z, av0.w},
                              {av1.x, av1.y, av1.z, av1.w},
                              {av2.x, av2.y, av2.z, av2.w},
                              {av3.x, av3.y, av3.z, av3.w}};
#pragma unroll
            for (int kk = 0; kk < 4; kk++) {
                float2 vv = *(const float2*)&vlm[(k + kk) * D_ + cg2];
#pragma unroll
                for (int i = 0; i < 4; i++) {
                    a2[i][0] += am[i][kk] * vv.x;
                    a2[i][1] += am[i][kk] * vv.y;
                }
            }
        }

        float* outp = ao + (size_t)(bh * N_ + t0 + rg) * D_ + cg2;
#pragma unroll
        for (int i = 0; i < 4; i++) {
            float rc = rec[rg + i];
            float2 st = make_float2(a2[i][0] * rc, a2[i][1] * rc);
            *(float2*)(outp + i * D_) = st;
        }
        __syncthreads();
    }
}

// ---------------------------------------------------------------------------
extern "C" void kernel_launch(void* const* d_in, const int* in_sizes, int n_in,
                              void* d_out, int out_size)
{
    (void)in_sizes; (void)n_in; (void)out_size;
    const float* x     = (const float*)d_in[0];
    const float* Wqkv  = (const float*)d_in[1];
    const float* E     = (const float*)d_in[2];
    const float* Wproj = (const float*)d_in[3];
    const float* bproj = (const float*)d_in[4];
    float* out = (float*)d_out;

    void *p_qkv, *p_klm, *p_vlm, *p_ao;
    void *p_xh, *p_xl, *p_w3h, *p_w3l, *p_aoh, *p_aol, *p_wph, *p_wpl;
    void *p_eh, *p_el, *p_kth, *p_ktl, *p_vth, *p_vtl;
    cudaGetSymbolAddress(&p_qkv, g_qkv);
    cudaGetSymbolAddress(&p_klm, g_klm);
    cudaGetSymbolAddress(&p_vlm, g_vlm);
    cudaGetSymbolAddress(&p_ao,  g_ao);
    cudaGetSymbolAddress(&p_xh,  g_xh);
    cudaGetSymbolAddress(&p_xl,  g_xl);
    cudaGetSymbolAddress(&p_w3h, g_w3h);
    cudaGetSymbolAddress(&p_w3l, g_w3l);
    cudaGetSymbolAddress(&p_aoh, g_aoh);
    cudaGetSymbolAddress(&p_aol, g_aol);
    cudaGetSymbolAddress(&p_wph, g_wph);
    cudaGetSymbolAddress(&p_wpl, g_wpl);
    cudaGetSymbolAddress(&p_eh,  g_eh);
    cudaGetSymbolAddress(&p_el,  g_el);
    cudaGetSymbolAddress(&p_kth, g_kth);
    cudaGetSymbolAddress(&p_ktl, g_ktl);
    cudaGetSymbolAddress(&p_vth, g_vth);
    cudaGetSymbolAddress(&p_vtl, g_vtl);

    float* qkv = (float*)p_qkv;
    float* klm = (float*)p_klm;
    float* vlm = (float*)p_vlm;
    float* ao  = (float*)p_ao;

    cudaFuncSetAttribute(attn_kernel, cudaFuncAttributeMaxDynamicSharedMemorySize,
                         ATTN_SMEM_BYTES);
    cudaFuncSetAttribute(gemm_mma_kernel, cudaFuncAttributeMaxDynamicSharedMemorySize,
                         GSMEM);
    cudaFuncSetAttribute(landmark_mma_kernel, cudaFuncAttributeMaxDynamicSharedMemorySize,
                         LSMEM);

    const int XN  = B_ * N_ * C_;
    const int W3N = C3_ * C_;
    const int WPN = C_ * C_;
    const int EN  = H_ * KL_ * N_;

    split_kernel<<<(XN / 4 + 255) / 256, 256>>>(x, (__nv_bfloat16*)p_xh,
                                                (__nv_bfloat16*)p_xl, XN / 4);
    split_kernel<<<(W3N / 4 + 255) / 256, 256>>>(Wqkv, (__nv_bfloat16*)p_w3h,
                                                 (__nv_bfloat16*)p_w3l, W3N / 4);
    split_kernel<<<(EN / 4 + 255) / 256, 256>>>(E, (__nv_bfloat16*)p_eh,
                                                (__nv_bfloat16*)p_el, EN / 4);

    // 1) qkv = x @ Wqkv^T
    gemm_mma_kernel<<<dim3(C3_ / 128, (B_ * N_) / 128), 256, GSMEM>>>(
        (__nv_bfloat16*)p_xh, (__nv_bfloat16*)p_xl,
        (__nv_bfloat16*)p_w3h, (__nv_bfloat16*)p_w3l, qkv, nullptr, C3_);

    // 2) K/V transpose-split
    kvsplit_kernel<<<64 * 64 * 2, 256>>>(qkv,
        (__nv_bfloat16*)p_kth, (__nv_bfloat16*)p_ktl,
        (__nv_bfloat16*)p_vth, (__nv_bfloat16*)p_vtl);

    // 3) landmark projections via MMA
    landmark_mma_kernel<<<128, 256, LSMEM>>>(
        (__nv_bfloat16*)p_eh, (__nv_bfloat16*)p_el,
        (__nv_bfloat16*)p_kth, (__nv_bfloat16*)p_ktl,
        (__nv_bfloat16*)p_vth, (__nv_bfloat16*)p_vtl, klm, vlm);

    // 4) fused attention
    attn_kernel<<<dim3(B_ * H_, 32), 256, ATTN_SMEM_BYTES>>>(qkv, klm, vlm, ao);

    split_kernel<<<(XN / 4 + 255) / 256, 256>>>(ao, (__nv_bfloat16*)p_aoh,
                                                (__nv_bfloat16*)p_aol, XN / 4);
    split_kernel<<<(WPN / 4 + 255) / 256, 256>>>(Wproj, (__nv_bfloat16*)p_wph,
                                                 (__nv_bfloat16*)p_wpl, WPN / 4);

    // 5) out = ao @ Wproj^T + bproj
    gemm_mma_kernel<<<dim3(C_ / 128, (B_ * N_) / 128), 256, GSMEM>>>(
        (__nv_bfloat16*)p_aoh, (__nv_bfloat16*)p_aol,
        (__nv_bfloat16*)p_wph, (__nv_bfloat16*)p_wpl, out, bproj, C_);
}